// round 9
// baseline (speedup 1.0000x reference)
#include <cuda_runtime.h>
#include <cuda_bf16.h>
#include <math.h>
#include <stdint.h>

#define SEQ   32768
#define DM    512
#define NCH   512
#define TCH   64
#define C_LN2 0.69314718055994531f

// ---------------- scratch (device globals) -----------------------------------
__device__ float g_xr  [(size_t)SEQ * 1024];
__device__ float g_u   [(size_t)SEQ * DM];
__device__ float g_xdbl[(size_t)SEQ * 36];
__device__ float g_dp  [(size_t)SEQ * DM];
__device__ float g_P   [NCH * 1024];
__device__ float g_S   [NCH * 1024];
__device__ float g_H   [NCH * 1024];
__device__ float g_csum[DM];

__device__ __nv_bfloat16 g_xh [(size_t)SEQ * DM], g_xl [(size_t)SEQ * DM];
__device__ __nv_bfloat16 g_uh [(size_t)SEQ * DM], g_ul [(size_t)SEQ * DM];
__device__ __nv_bfloat16 g_dh [(size_t)SEQ * DM];
__device__ __nv_bfloat16 g_yh [(size_t)SEQ * DM], g_yl [(size_t)SEQ * DM];
__device__ __nv_bfloat16 g_wih[1024 * 512],       g_wil[1024 * 512];
__device__ __nv_bfloat16 g_dsh[512 * 512],        g_dsl[512 * 512];
__device__ __nv_bfloat16 g_woh[512 * 512],        g_wol[512 * 512];
__device__ __nv_bfloat16 g_xph[128 * 512],        g_xpl[128 * 512];

// ---------------- PTX helpers ---------------------------------------------------
__device__ __forceinline__ uint32_t smem_u32(const void* p) {
    uint32_t a;
    asm("{ .reg .u64 t; cvta.to.shared.u64 t, %1; cvt.u32.u64 %0, t; }" : "=r"(a) : "l"(p));
    return a;
}
#define CP_ASYNC16(dst, src) \
    asm volatile("cp.async.cg.shared.global [%0], [%1], 16;" :: "r"(dst), "l"(src) : "memory")
#define CP_COMMIT() asm volatile("cp.async.commit_group;" ::: "memory")
#define CP_WAIT1()  asm volatile("cp.async.wait_group 1;" ::: "memory")

__device__ __forceinline__ void ldsm4(uint32_t* r, uint32_t addr) {
    asm volatile("ldmatrix.sync.aligned.m8n8.x4.shared.b16 {%0,%1,%2,%3}, [%4];"
                 : "=r"(r[0]), "=r"(r[1]), "=r"(r[2]), "=r"(r[3]) : "r"(addr));
}
__device__ __forceinline__ void mma16816(float* c, const uint32_t* a,
                                         uint32_t b0, uint32_t b1) {
    asm volatile("mma.sync.aligned.m16n8k16.row.col.f32.bf16.bf16.f32 "
                 "{%0,%1,%2,%3}, {%4,%5,%6,%7}, {%8,%9}, {%0,%1,%2,%3};"
                 : "+f"(c[0]), "+f"(c[1]), "+f"(c[2]), "+f"(c[3])
                 : "r"(a[0]), "r"(a[1]), "r"(a[2]), "r"(a[3]), "r"(b0), "r"(b1));
}

// ---------------- math helpers --------------------------------------------------
__device__ __forceinline__ float softplusf(float x) {
    float ax = fabsf(x);
    if (ax < 0.25f) {
        float x2 = x * x;
        return C_LN2 + 0.5f * x
             + x2 * (0.125f + x2 * (-1.0f/192.0f + x2 * (1.0f/2880.0f)));
    }
    return fmaxf(x, 0.0f) + log1pf(expf(-ax));
}
__device__ __forceinline__ float siluf(float x) { return x / (1.0f + __expf(-x)); }
__device__ __forceinline__ void split_bf16(float v, __nv_bfloat16& h, __nv_bfloat16& l) {
    h = __float2bfloat16(v);
    l = __float2bfloat16(v - __bfloat162float(h));
}

// ---------------- combined split conversion kernel ------------------------------
__global__ __launch_bounds__(256)
void cvt_all(const float* __restrict__ x, const float* __restrict__ inw,
             const float* __restrict__ outw, const float* __restrict__ dis,
             const float* __restrict__ xpw)
{
    int b = blockIdx.x;
    if (b < 16384) {
        int i = b * 256 + threadIdx.x;
        float4 v = reinterpret_cast<const float4*>(x)[i];
        __nv_bfloat16 h[4], l[4];
        split_bf16(v.x, h[0], l[0]); split_bf16(v.y, h[1], l[1]);
        split_bf16(v.z, h[2], l[2]); split_bf16(v.w, h[3], l[3]);
        reinterpret_cast<uint2*>(g_xh)[i] = *reinterpret_cast<uint2*>(h);
        reinterpret_cast<uint2*>(g_xl)[i] = *reinterpret_cast<uint2*>(l);
    } else if (b < 16896) {
        int i = (b - 16384) * 256 + threadIdx.x;
        float4 v = reinterpret_cast<const float4*>(inw)[i];
        __nv_bfloat16 h[4], l[4];
        split_bf16(v.x, h[0], l[0]); split_bf16(v.y, h[1], l[1]);
        split_bf16(v.z, h[2], l[2]); split_bf16(v.w, h[3], l[3]);
        reinterpret_cast<uint2*>(g_wih)[i] = *reinterpret_cast<uint2*>(h);
        reinterpret_cast<uint2*>(g_wil)[i] = *reinterpret_cast<uint2*>(l);
    } else if (b < 17152) {
        int i = (b - 16896) * 256 + threadIdx.x;
        float4 v = reinterpret_cast<const float4*>(outw)[i];
        __nv_bfloat16 h[4], l[4];
        split_bf16(v.x, h[0], l[0]); split_bf16(v.y, h[1], l[1]);
        split_bf16(v.z, h[2], l[2]); split_bf16(v.w, h[3], l[3]);
        reinterpret_cast<uint2*>(g_woh)[i] = *reinterpret_cast<uint2*>(h);
        reinterpret_cast<uint2*>(g_wol)[i] = *reinterpret_cast<uint2*>(l);
    } else if (b < 18176) {
        int idx = (b - 17152) * 256 + threadIdx.x;
        int n = idx >> 9, k = idx & 511;
        __nv_bfloat16 h, l;
        split_bf16(dis[k * 512 + n], h, l);
        g_dsh[idx] = h; g_dsl[idx] = l;
    } else {
        int idx = (b - 18176) * 256 + threadIdx.x;
        int r = idx >> 9;
        __nv_bfloat16 h = __float2bfloat16(0.0f), l = h;
        if (r < 36) split_bf16(xpw[idx], h, l);
        g_xph[idx] = h; g_xpl[idx] = l;
    }
}

// ---------------- colsum of dis (for rank-1 delta_p term) ------------------------
__global__ __launch_bounds__(256)
void colsum_kernel(const float* __restrict__ dis)
{
    int n = blockIdx.x * 256 + threadIdx.x;
    float s = 0.0f;
    #pragma unroll 8
    for (int k = 0; k < 512; k++) s += dis[k * 512 + n];
    g_csum[n] = s * C_LN2;
}

// ---------------- mma.sync bf16 GEMM ---------------------------------------------
// TERMS=3: C = (Ah+Al)@(Bh+Bl)^T (3-term).  TERMS=1: C = Ah@Bh^T.
// CTA 128x128, 512 threads (16 warps, 4m x 4n), warp tile 32x32, BK=32, 2 stages.
// Per stage: ldsm ALL fragments -> sync -> prefetch (overlaps mma) -> mma burst.
// EPI: 0 plain, 1 finite filter, 2 narrow store (cols<ldc), 3 += bias2[col]
#define PITCH   80
#define STAGE_B 40960
template <int EPI, int TERMS>
__global__ __launch_bounds__(512, 1)
void mma_gemm(const __nv_bfloat16* __restrict__ Ah, const __nv_bfloat16* __restrict__ Al,
              const __nv_bfloat16* __restrict__ Bh, const __nv_bfloat16* __restrict__ Bl,
              float* __restrict__ C, const float* __restrict__ bias2,
              int N, int K, int ldc)
{
    extern __shared__ char dsm[];
    const uint32_t sb = smem_u32(dsm);
    const int tid = threadIdx.x;
    const int wid = tid >> 5, L = tid & 31;
    const int wm = wid >> 2, wn = wid & 3;          // 4m x 4n warps
    const int m0 = blockIdx.y * 128, n0 = blockIdx.x * 128;

    const __nv_bfloat16* srcA[2] = { Ah + (size_t)m0 * K,
                                     (TERMS == 3 ? Al : Ah) + (size_t)m0 * K };
    const __nv_bfloat16* srcB[2] = { Bh + (size_t)n0 * K,
                                     (TERMS == 3 ? Bl : Bh) + (size_t)n0 * K };

    const int lrow = L & 15;
    const int lcolB = (L >> 4) * 16;
    const uint32_t aBase = sb + (wm * 32 + lrow) * PITCH + lcolB;            // Ah @ 0
    const uint32_t bBase = sb + 20480 + (wn * 32 + lrow) * PITCH + lcolB;    // Bh @ 20480

    float acc[2][4][4];
    #pragma unroll
    for (int i = 0; i < 2; i++)
        #pragma unroll
        for (int j = 0; j < 4; j++)
            #pragma unroll
            for (int q = 0; q < 4; q++) acc[i][j][q] = 0.0f;

    const int nk = K / 32;

    auto load_stage = [&](int ks, int buf) {
        uint32_t dst0 = sb + buf * STAGE_B;
        int k0 = ks * 32;
        if (TERMS == 3) {
            #pragma unroll
            for (int it = 0; it < 4; it++) {
                int cid = it * 512 + tid;
                int mat = cid >> 9, w = cid & 511;
                int r = w >> 2, c = w & 3;
                uint32_t dst = dst0 + mat * 10240 + r * PITCH + c * 16;
                const __nv_bfloat16* src =
                    (mat < 2 ? srcA[mat] : srcB[mat - 2]) + (size_t)r * K + k0 + c * 8;
                CP_ASYNC16(dst, src);
            }
        } else {
            #pragma unroll
            for (int it = 0; it < 2; it++) {
                int cid = it * 512 + tid;
                int isB = cid >> 9, w = cid & 511;
                int r = w >> 2, c = w & 3;
                uint32_t dst = dst0 + isB * 20480 + r * PITCH + c * 16;
                const __nv_bfloat16* src =
                    (isB ? srcB[0] : srcA[0]) + (size_t)r * K + k0 + c * 8;
                CP_ASYNC16(dst, src);
            }
        }
    };

    load_stage(0, 0); CP_COMMIT();
    load_stage(1, 1); CP_COMMIT();

    for (int ks = 0; ks < nk; ks++) {
        CP_WAIT1();
        __syncthreads();
        uint32_t bo = (ks & 1) * STAGE_B;

        // ---- load ALL fragments for this stage (both kk halves) ----
        uint32_t ah[2][2][4], al[2][2][4], bh[2][2][4], bl[2][2][4];
        #pragma unroll
        for (int kk = 0; kk < 2; kk++) {
            uint32_t ko = kk * 32;
            #pragma unroll
            for (int mi = 0; mi < 2; mi++) {
                ldsm4(ah[kk][mi], aBase + bo + mi * 1280 + ko);
                if (TERMS == 3) ldsm4(al[kk][mi], aBase + bo + 10240 + mi * 1280 + ko);
            }
            #pragma unroll
            for (int t = 0; t < 2; t++) {
                ldsm4(bh[kk][t], bBase + bo + t * 1280 + ko);
                if (TERMS == 3) ldsm4(bl[kk][t], bBase + bo + 10240 + t * 1280 + ko);
            }
        }
        __syncthreads();                 // all reads done -> safe to overwrite
        if (ks + 2 < nk) load_stage(ks + 2, ks & 1);
        CP_COMMIT();

        // ---- mma burst ----
        #pragma unroll
        for (int kk = 0; kk < 2; kk++)
            #pragma unroll
            for (int mi = 0; mi < 2; mi++)
                #pragma unroll
                for (int t = 0; t < 2; t++) {
                    mma16816(acc[mi][2*t+0], ah[kk][mi], bh[kk][t][0], bh[kk][t][2]);
                    mma16816(acc[mi][2*t+1], ah[kk][mi], bh[kk][t][1], bh[kk][t][3]);
                    if (TERMS == 3) {
                        mma16816(acc[mi][2*t+0], al[kk][mi], bh[kk][t][0], bh[kk][t][2]);
                        mma16816(acc[mi][2*t+1], al[kk][mi], bh[kk][t][1], bh[kk][t][3]);
                        mma16816(acc[mi][2*t+0], ah[kk][mi], bl[kk][t][0], bl[kk][t][2]);
                        mma16816(acc[mi][2*t+1], ah[kk][mi], bl[kk][t][1], bl[kk][t][3]);
                    }
                }
    }

    // epilogue
    #pragma unroll
    for (int mi = 0; mi < 2; mi++) {
        #pragma unroll
        for (int j = 0; j < 4; j++) {
            int row = m0 + wm * 32 + mi * 16 + (L >> 2);
            int col = n0 + wn * 32 + j * 8 + (L & 3) * 2;
            float v0 = acc[mi][j][0], v1 = acc[mi][j][1];
            float v2 = acc[mi][j][2], v3 = acc[mi][j][3];
            if (EPI == 1) {
                v0 = isfinite(v0) ? v0 : 0.0f; v1 = isfinite(v1) ? v1 : 0.0f;
                v2 = isfinite(v2) ? v2 : 0.0f; v3 = isfinite(v3) ? v3 : 0.0f;
            }
            if (EPI == 3) {
                float b0 = bias2[col], b1 = bias2[col + 1];
                v0 += b0; v1 += b1; v2 += b0; v3 += b1;
            }
            if (EPI == 2) {
                if (col + 1 < ldc) {
                    *reinterpret_cast<float2*>(C + (size_t)row * ldc + col)       = make_float2(v0, v1);
                    *reinterpret_cast<float2*>(C + (size_t)(row + 8) * ldc + col) = make_float2(v2, v3);
                }
            } else {
                *reinterpret_cast<float2*>(C + (size_t)row * ldc + col)       = make_float2(v0, v1);
                *reinterpret_cast<float2*>(C + (size_t)(row + 8) * ldc + col) = make_float2(v2, v3);
            }
        }
    }
}

// ---------------- SIMT GEMM (dt_proj: K=32, softplus, bf16 residual output) -----
__global__ __launch_bounds__(256)
void dtproj_kernel(const float* __restrict__ A,
                   const float* __restrict__ B,
                   const float* __restrict__ bias,
                   __nv_bfloat16* __restrict__ Chi)
{
    __shared__ float As[8][128];
    __shared__ float Bs[8][128];
    const int tid = threadIdx.x;
    const int m0 = blockIdx.y * 128, n0 = blockIdx.x * 128;
    const int tr = tid / 16, tc = tid % 16;
    const int K = 32, N = 512, lda = 36;

    float acc[8][8];
    #pragma unroll
    for (int i = 0; i < 8; i++)
        #pragma unroll
        for (int j = 0; j < 8; j++) acc[i][j] = 0.0f;

    for (int k0 = 0; k0 < K; k0 += 8) {
        {
            int row = tid >> 1, kq = (tid & 1) * 4;
            float4 v = *reinterpret_cast<const float4*>(A + (size_t)(m0 + row) * lda + k0 + kq);
            As[kq+0][row] = v.x; As[kq+1][row] = v.y; As[kq+2][row] = v.z; As[kq+3][row] = v.w;
        }
        {
            int row = tid >> 1, kq = (tid & 1) * 4;
            float4 v = *reinterpret_cast<const float4*>(B + (size_t)(n0 + row) * K + k0 + kq);
            Bs[kq+0][row] = v.x; Bs[kq+1][row] = v.y; Bs[kq+2][row] = v.z; Bs[kq+3][row] = v.w;
        }
        __syncthreads();
        #pragma unroll
        for (int k = 0; k < 8; k++) {
            float ra[8], rb[8];
            *reinterpret_cast<float4*>(&ra[0]) = *reinterpret_cast<const float4*>(&As[k][tr*8]);
            *reinterpret_cast<float4*>(&ra[4]) = *reinterpret_cast<const float4*>(&As[k][tr*8+4]);
            *reinterpret_cast<float4*>(&rb[0]) = *reinterpret_cast<const float4*>(&Bs[k][tc*8]);
            *reinterpret_cast<float4*>(&rb[4]) = *reinterpret_cast<const float4*>(&Bs[k][tc*8+4]);
            #pragma unroll
            for (int i = 0; i < 8; i++)
                #pragma unroll
                for (int j = 0; j < 8; j++)
                    acc[i][j] = fmaf(ra[i], rb[j], acc[i][j]);
        }
        __syncthreads();
    }
    #pragma unroll
    for (int i = 0; i < 8; i++) {
        size_t m = (size_t)(m0 + tr * 8 + i);
        __nv_bfloat16 ho[8];
        #pragma unroll
        for (int j = 0; j < 8; j++) {
            float v = softplusf(acc[i][j] + bias[n0 + tc * 8 + j]) - C_LN2;
            ho[j] = __float2bfloat16(v);
        }
        *reinterpret_cast<uint4*>(Chi + m * N + n0 + tc * 8) = *reinterpret_cast<uint4*>(ho);
    }
}

// ---------------- depthwise conv + silu: 4 timesteps x 4 channels per thread -----
__global__ __launch_bounds__(256)
void conv_silu_kernel(const float* __restrict__ cw, const float* __restrict__ cb)
{
    int g = blockIdx.x * 256 + threadIdx.x;    // over (SEQ/4) * 128
    int t0 = (g >> 7) * 4;
    int d4 = (g & 127) * 4;
    const float* base = g_xr + d4;

    float4 row[7];                              // x[t0-3 .. t0+3]
    #pragma unroll
    for (int k = 0; k < 7; k++) {
        int t = t0 - 3 + k;
        row[k] = (t >= 0) ? *reinterpret_cast<const float4*>(base + (size_t)t * 1024)
                          : make_float4(0.f, 0.f, 0.f, 0.f);
    }
    float4 bv = *reinterpret_cast<const float4*>(cb + d4);
    const float* bb = &bv.x;
    float4 w[4];
    #pragma unroll
    for (int j = 0; j < 4; j++) w[j] = reinterpret_cast<const float4*>(cw)[d4 + j];

    #pragma unroll
    for (int i = 0; i < 4; i++) {               // output timestep t0+i
        float u[4];
        #pragma unroll
        for (int j = 0; j < 4; j++) {
            float a = bb[j];
            a = fmaf(w[j].x, (&row[i+0].x)[j], a);
            a = fmaf(w[j].y, (&row[i+1].x)[j], a);
            a = fmaf(w[j].z, (&row[i+2].x)[j], a);
            a = fmaf(w[j].w, (&row[i+3].x)[j], a);
            u[j] = siluf(a);
        }
        size_t o = (size_t)(t0 + i) * 512 + d4;
        *reinterpret_cast<float4*>(g_u + o) = make_float4(u[0], u[1], u[2], u[3]);
        __nv_bfloat16 h[4], l[4];
        #pragma unroll
        for (int j = 0; j < 4; j++) split_bf16(u[j], h[j], l[j]);
        *reinterpret_cast<uint2*>(g_uh + o) = *reinterpret_cast<uint2*>(h);
        *reinterpret_cast<uint2*>(g_ul + o) = *reinterpret_cast<uint2*>(l);
    }
}

// ---------------- scan passes (TCH=64, thread = 4 channels) ----------------------
__global__ __launch_bounds__(128)
void scanA_kernel(const float* __restrict__ Alog)
{
    int c  = blockIdx.x;
    int d4 = threadIdx.x * 4;
    float A0[4], A1[4], P0[4], P1[4], S0[4], S1[4];
    #pragma unroll
    for (int j = 0; j < 4; j++) {
        A0[j] = -expf(Alog[(d4 + j) * 2 + 0]);
        A1[j] = -expf(Alog[(d4 + j) * 2 + 1]);
        P0[j] = 1.f; P1[j] = 1.f; S0[j] = 0.f; S1[j] = 0.f;
    }
    const float* dp = g_dp + (size_t)c * TCH * DM + d4;
    const float* uu = g_u  + (size_t)c * TCH * DM + d4;
    const float* xd = g_xdbl + (size_t)c * TCH * 36;
    #pragma unroll 4
    for (int i = 0; i < TCH; i++) {
        float4 dpv = *reinterpret_cast<const float4*>(dp + (size_t)i * DM);
        float4 uv  = *reinterpret_cast<const float4*>(uu + (size_t)i * DM);
        float B0 = xd[i * 36 + 32], B1 = xd[i * 36 + 33];
        const float* dj = &dpv.x; const float* uj = &uv.x;
        #pragma unroll
        for (int j = 0; j < 4; j++) {
            float x0 = dj[j] * A0[j], x1 = dj[j] * A1[j];
            float a0 = 0.f, a1 = 0.f;
            if (fmaxf(x0, x1) > -87.0f) { a0 = __expf(x0); a1 = __expf(x1); }
            float bu = dj[j] * uj[j];
            S0[j] = fmaf(a0, S0[j], bu * B0);
            S1[j] = fmaf(a1, S1[j], bu * B1);
            P0[j] *= a0; P1[j] *= a1;
        }
    }
    #pragma unroll
    for (int j = 0; j < 4; j++) {
        int dn = (d4 + j) * 2;
        g_P[c * 1024 + dn] = P0[j]; g_P[c * 1024 + dn + 1] = P1[j];
        g_S[c * 1024 + dn] = S0[j]; g_S[c * 1024 + dn + 1] = S1[j];
    }
}

__global__ __launch_bounds__(128)
void scanB_kernel()
{
    int dn = blockIdx.x * 128 + threadIdx.x;
    float h = 0.0f;
    for (int cb = 0; cb < NCH; cb += 16) {
        float p[16], s[16];
        #pragma unroll
        for (int i = 0; i < 16; i++) {
            p[i] = g_P[(cb + i) * 1024 + dn];
            s[i] = g_S[(cb + i) * 1024 + dn];
        }
        #pragma unroll
        for (int i = 0; i < 16; i++) {
            g_H[(cb + i) * 1024 + dn] = h;
            h = fmaf(p[i], h, s[i]);
        }
    }
}

__global__ __launch_bounds__(128)
void scanC_kernel(const float* __restrict__ Alog, const float* __restrict__ Dw)
{
    int c  = blockIdx.x;
    int d4 = threadIdx.x * 4;
    float A0[4], A1[4], h0[4], h1[4];
    #pragma unroll
    for (int j = 0; j < 4; j++) {
        A0[j] = -expf(Alog[(d4 + j) * 2 + 0]);
        A1[j] = -expf(Alog[(d4 + j) * 2 + 1]);
        h0[j] = g_H[c * 1024 + (d4 + j) * 2];
        h1[j] = g_H[c * 1024 + (d4 + j) * 2 + 1];
    }
    float4 Dv4 = *reinterpret_cast<const float4*>(Dw + d4);
    const float* Dv = &Dv4.x;
    const float* dp = g_dp + (size_t)c * TCH * DM + d4;
    const float* uu = g_u  + (size_t)c * TCH * DM + d4;
    const float* xd = g_xdbl + (size_t)c * TCH * 36;
    const float* rs = g_xr + (size_t)c * TCH * 1024 + 512 + d4;
    __nv_bfloat16* yh = g_yh + (size_t)c * TCH * DM + d4;
    __nv_bfloat16* yl = g_yl + (size_t)c * TCH * DM + d4;
    #pragma unroll 4
    for (int i = 0; i < TCH; i++) {
        float4 dpv = *reinterpret_cast<const float4*>(dp + (size_t)i * DM);
        float4 uv  = *reinterpret_cast<const float4*>(uu + (size_t)i * DM);
        float4 rv  = *reinterpret_cast<const float4*>(rs + (size_t)i * 1024);
        float B0 = xd[i * 36 + 32], B1 = xd[i * 36 + 33];
        float C0 = xd[i * 36 + 34], C1 = xd[i * 36 + 35];
        const float* dj = &dpv.x; const float* uj = &uv.x; const float* rj = &rv.x;
        __nv_bfloat16 oh[4], ol[4];
        #pragma unroll
        for (int j = 0; j < 4; j++) {
            float x0 = dj[j] * A0[j], x1 = dj[j] * A1[j];
            float a0 = 0.f, a1 = 0.f;
            if (fmaxf(x0, x1) > -87.0f) { a0 = __expf(x0); a1 = __expf(x1); }
            float bu = dj[j] * uj[j];
            h0[j] = fmaf(a0, h0[j], bu * B0);
            h1[j] = fmaf(a1, h1[j], bu * B1);
            float y = fmaf(h0[j], C0, fmaf(h1[j], C1, uj[j] * Dv[j]));
            y *= siluf(rj[j]);
            split_bf16(y, oh[j], ol[j]);
        }
        *reinterpret_cast<uint2*>(yh + (size_t)i * DM) = *reinterpret_cast<uint2*>(oh);
        *reinterpret_cast<uint2*>(yl + (size_t)i * DM) = *reinterpret_cast<uint2*>(ol);
    }
}

// ---------------- launch --------------------------------------------------------
extern "C" void kernel_launch(void* const* d_in, const int* in_sizes, int n_in,
                              void* d_out, int out_size)
{
    const float* x     = (const float*)d_in[0];
    const float* dis   = (const float*)d_in[1];
    const float* inw   = (const float*)d_in[2];
    const float* convw = (const float*)d_in[3];
    const float* convb = (const float*)d_in[4];
    const float* xpw   = (const float*)d_in[5];
    const float* dtw   = (const float*)d_in[6];
    const float* dtb   = (const float*)d_in[7];
    const float* alog  = (const float*)d_in[8];
    const float* Dw    = (const float*)d_in[9];
    const float* outw  = (const float*)d_in[10];
    float* out = (float*)d_out;

    float *xr, *dp, *xdbl, *csum;
    __nv_bfloat16 *xh, *xl, *uh, *ul, *dh, *yh, *yl;
    __nv_bfloat16 *wih, *wil, *dsh, *dsl, *woh, *wol, *xph, *xpl;
    cudaGetSymbolAddress((void**)&xr,   g_xr);
    cudaGetSymbolAddress((void**)&dp,   g_dp);
    cudaGetSymbolAddress((void**)&xdbl, g_xdbl);
    cudaGetSymbolAddress((void**)&csum, g_csum);
    cudaGetSymbolAddress((void**)&xh,  g_xh);  cudaGetSymbolAddress((void**)&xl,  g_xl);
    cudaGetSymbolAddress((void**)&uh,  g_uh);  cudaGetSymbolAddress((void**)&ul,  g_ul);
    cudaGetSymbolAddress((void**)&dh,  g_dh);
    cudaGetSymbolAddress((void**)&yh,  g_yh);  cudaGetSymbolAddress((void**)&yl,  g_yl);
    cudaGetSymbolAddress((void**)&wih, g_wih); cudaGetSymbolAddress((void**)&wil, g_wil);
    cudaGetSymbolAddress((void**)&dsh, g_dsh); cudaGetSymbolAddress((void**)&dsl, g_dsl);
    cudaGetSymbolAddress((void**)&woh, g_woh); cudaGetSymbolAddress((void**)&wol, g_wol);
    cudaGetSymbolAddress((void**)&xph, g_xph); cudaGetSymbolAddress((void**)&xpl, g_xpl);

    const int GEMM_SMEM = 2 * STAGE_B;   // 81920
    cudaFuncSetAttribute((const void*)mma_gemm<0,3>, cudaFuncAttributeMaxDynamicSharedMemorySize, GEMM_SMEM);
    cudaFuncSetAttribute((const void*)mma_gemm<1,3>, cudaFuncAttributeMaxDynamicSharedMemorySize, GEMM_SMEM);
    cudaFuncSetAttribute((const void*)mma_gemm<2,3>, cudaFuncAttributeMaxDynamicSharedMemorySize, GEMM_SMEM);
    cudaFuncSetAttribute((const void*)mma_gemm<3,1>, cudaFuncAttributeMaxDynamicSharedMemorySize, GEMM_SMEM);

    // 0) all split conversions + dis colsum
    cvt_all<<<18432, 256>>>(x, inw, outw, dis, xpw);
    colsum_kernel<<<2, 256>>>(dis);

    // 1) xr = x @ in_proj_w^T   [32768 x 1024]
    mma_gemm<0,3><<<dim3(8, SEQ / 128), 512, GEMM_SMEM>>>(xh, xl, wih, wil, xr, nullptr, 1024, 512, 1024);

    // 2) u = silu(conv(xs))  (+ bf16 split), 4 timesteps/thread
    conv_silu_kernel<<<(SEQ / 4 * 128) / 256, 256>>>(convw, convb);

    // 3) xdbl = u @ x_proj_w^T  (N padded to 128, store cols<36)
    mma_gemm<2,3><<<dim3(1, SEQ / 128), 512, GEMM_SMEM>>>(uh, ul, xph, xpl, xdbl, nullptr, 128, 512, 36);

    // 4) delta residual = softplus(xdbl[:, :32] @ dt_proj_w^T + b) - ln2 -> bf16
    dtproj_kernel<<<dim3(DM / 128, SEQ / 128), 256>>>(g_xdbl, dtw, dtb, dh);

    // 5) delta_p = ln2*colsum(dis) + residual @ dis
    mma_gemm<3,1><<<dim3(DM / 128, SEQ / 128), 512, GEMM_SMEM>>>(dh, nullptr, dsh, nullptr, dp, csum, DM, 512, DM);

    // 6-8) chunked selective scan
    scanA_kernel<<<NCH, 128>>>(alog);
    scanB_kernel<<<8, 128>>>();
    scanC_kernel<<<NCH, 128>>>(alog, Dw);

    // 9) out = y @ out_proj_w^T, finite filter
    mma_gemm<1,3><<<dim3(DM / 128, SEQ / 128), 512, GEMM_SMEM>>>(yh, yl, woh, wol, out, nullptr, DM, 512, DM);
}

// round 10
// speedup vs baseline: 1.5407x; 1.5407x over previous
#include <cuda_runtime.h>
#include <cuda_bf16.h>
#include <math.h>
#include <stdint.h>

#define SEQ   32768
#define DM    512
#define NCH   512
#define TCH   64
#define C_LN2 0.69314718055994531f

// ---------------- scratch (device globals) -----------------------------------
__device__ float g_xr  [(size_t)SEQ * 1024];
__device__ float g_u   [(size_t)SEQ * DM];
__device__ float g_xdbl[(size_t)SEQ * 36];
__device__ float g_dp  [(size_t)SEQ * DM];
__device__ float g_P   [NCH * 1024];
__device__ float g_S   [NCH * 1024];
__device__ float g_H   [NCH * 1024];
__device__ float g_csum[DM];

__device__ __nv_bfloat16 g_xh [(size_t)SEQ * DM], g_xl [(size_t)SEQ * DM];
__device__ __nv_bfloat16 g_uh [(size_t)SEQ * DM], g_ul [(size_t)SEQ * DM];
__device__ __nv_bfloat16 g_dh [(size_t)SEQ * DM];
__device__ __nv_bfloat16 g_yh [(size_t)SEQ * DM], g_yl [(size_t)SEQ * DM];
__device__ __nv_bfloat16 g_wih[1024 * 512],       g_wil[1024 * 512];
__device__ __nv_bfloat16 g_dsh[512 * 512],        g_dsl[512 * 512];
__device__ __nv_bfloat16 g_woh[512 * 512],        g_wol[512 * 512];
__device__ __nv_bfloat16 g_xph[128 * 512],        g_xpl[128 * 512];

// ---------------- PTX helpers ---------------------------------------------------
__device__ __forceinline__ uint32_t smem_u32(const void* p) {
    uint32_t a;
    asm("{ .reg .u64 t; cvta.to.shared.u64 t, %1; cvt.u32.u64 %0, t; }" : "=r"(a) : "l"(p));
    return a;
}
#define CP_ASYNC16(dst, src) \
    asm volatile("cp.async.cg.shared.global [%0], [%1], 16;" :: "r"(dst), "l"(src) : "memory")
#define CP_COMMIT() asm volatile("cp.async.commit_group;" ::: "memory")
#define CP_WAIT1()  asm volatile("cp.async.wait_group 1;" ::: "memory")

__device__ __forceinline__ void ldsm4(uint32_t* r, uint32_t addr) {
    asm volatile("ldmatrix.sync.aligned.m8n8.x4.shared.b16 {%0,%1,%2,%3}, [%4];"
                 : "=r"(r[0]), "=r"(r[1]), "=r"(r[2]), "=r"(r[3]) : "r"(addr));
}
__device__ __forceinline__ void mma16816(float* c, const uint32_t* a,
                                         uint32_t b0, uint32_t b1) {
    asm volatile("mma.sync.aligned.m16n8k16.row.col.f32.bf16.bf16.f32 "
                 "{%0,%1,%2,%3}, {%4,%5,%6,%7}, {%8,%9}, {%0,%1,%2,%3};"
                 : "+f"(c[0]), "+f"(c[1]), "+f"(c[2]), "+f"(c[3])
                 : "r"(a[0]), "r"(a[1]), "r"(a[2]), "r"(a[3]), "r"(b0), "r"(b1));
}

// ---------------- math helpers --------------------------------------------------
__device__ __forceinline__ float softplusf(float x) {
    float ax = fabsf(x);
    if (ax < 0.25f) {
        float x2 = x * x;
        return C_LN2 + 0.5f * x
             + x2 * (0.125f + x2 * (-1.0f/192.0f + x2 * (1.0f/2880.0f)));
    }
    return fmaxf(x, 0.0f) + log1pf(expf(-ax));
}
__device__ __forceinline__ float siluf(float x) { return x / (1.0f + __expf(-x)); }
__device__ __forceinline__ void split_bf16(float v, __nv_bfloat16& h, __nv_bfloat16& l) {
    h = __float2bfloat16(v);
    l = __float2bfloat16(v - __bfloat162float(h));
}

// ---------------- combined split conversion kernel ------------------------------
__global__ __launch_bounds__(256)
void cvt_all(const float* __restrict__ x, const float* __restrict__ inw,
             const float* __restrict__ outw, const float* __restrict__ dis,
             const float* __restrict__ xpw)
{
    int b = blockIdx.x;
    if (b < 16384) {
        int i = b * 256 + threadIdx.x;
        float4 v = reinterpret_cast<const float4*>(x)[i];
        __nv_bfloat16 h[4], l[4];
        split_bf16(v.x, h[0], l[0]); split_bf16(v.y, h[1], l[1]);
        split_bf16(v.z, h[2], l[2]); split_bf16(v.w, h[3], l[3]);
        reinterpret_cast<uint2*>(g_xh)[i] = *reinterpret_cast<uint2*>(h);
        reinterpret_cast<uint2*>(g_xl)[i] = *reinterpret_cast<uint2*>(l);
    } else if (b < 16896) {
        int i = (b - 16384) * 256 + threadIdx.x;
        float4 v = reinterpret_cast<const float4*>(inw)[i];
        __nv_bfloat16 h[4], l[4];
        split_bf16(v.x, h[0], l[0]); split_bf16(v.y, h[1], l[1]);
        split_bf16(v.z, h[2], l[2]); split_bf16(v.w, h[3], l[3]);
        reinterpret_cast<uint2*>(g_wih)[i] = *reinterpret_cast<uint2*>(h);
        reinterpret_cast<uint2*>(g_wil)[i] = *reinterpret_cast<uint2*>(l);
    } else if (b < 17152) {
        int i = (b - 16896) * 256 + threadIdx.x;
        float4 v = reinterpret_cast<const float4*>(outw)[i];
        __nv_bfloat16 h[4], l[4];
        split_bf16(v.x, h[0], l[0]); split_bf16(v.y, h[1], l[1]);
        split_bf16(v.z, h[2], l[2]); split_bf16(v.w, h[3], l[3]);
        reinterpret_cast<uint2*>(g_woh)[i] = *reinterpret_cast<uint2*>(h);
        reinterpret_cast<uint2*>(g_wol)[i] = *reinterpret_cast<uint2*>(l);
    } else if (b < 18176) {
        int idx = (b - 17152) * 256 + threadIdx.x;
        int n = idx >> 9, k = idx & 511;
        __nv_bfloat16 h, l;
        split_bf16(dis[k * 512 + n], h, l);
        g_dsh[idx] = h; g_dsl[idx] = l;
    } else {
        int idx = (b - 18176) * 256 + threadIdx.x;
        int r = idx >> 9;
        __nv_bfloat16 h = __float2bfloat16(0.0f), l = h;
        if (r < 36) split_bf16(xpw[idx], h, l);
        g_xph[idx] = h; g_xpl[idx] = l;
    }
}

// ---------------- colsum of dis (for rank-1 delta_p term) ------------------------
__global__ __launch_bounds__(256)
void colsum_kernel(const float* __restrict__ dis)
{
    int n = blockIdx.x * 256 + threadIdx.x;
    float s = 0.0f;
    #pragma unroll 8
    for (int k = 0; k < 512; k++) s += dis[k * 512 + n];
    g_csum[n] = s * C_LN2;
}

// ---------------- mma.sync bf16 GEMM (R8 config — known best) --------------------
// TERMS=3: C = (Ah+Al)@(Bh+Bl)^T.  TERMS=1: C = Ah@Bh^T.
// CTA 128x128, 256 threads (8 warps, 4m x 2n), warp tile 32x64, BK=32, 2 stages.
// EPI: 0 plain, 1 finite filter, 2 narrow store (cols<ldc), 3 += bias2[col]
#define PITCH   80
#define STAGE_B 40960
template <int EPI, int TERMS>
__global__ __launch_bounds__(256, 2)
void mma_gemm(const __nv_bfloat16* __restrict__ Ah, const __nv_bfloat16* __restrict__ Al,
              const __nv_bfloat16* __restrict__ Bh, const __nv_bfloat16* __restrict__ Bl,
              float* __restrict__ C, const float* __restrict__ bias2,
              int N, int K, int ldc)
{
    extern __shared__ char dsm[];
    const uint32_t sb = smem_u32(dsm);
    const int tid = threadIdx.x;
    const int wid = tid >> 5, L = tid & 31;
    const int wm = wid >> 1, wn = wid & 1;
    const int m0 = blockIdx.y * 128, n0 = blockIdx.x * 128;

    const __nv_bfloat16* srcA[2] = { Ah + (size_t)m0 * K,
                                     (TERMS == 3 ? Al : Ah) + (size_t)m0 * K };
    const __nv_bfloat16* srcB[2] = { Bh + (size_t)n0 * K,
                                     (TERMS == 3 ? Bl : Bh) + (size_t)n0 * K };

    const int lrow = L & 15;
    const int lcolB = (L >> 4) * 16;
    const uint32_t aBase = sb + (wm * 32 + lrow) * PITCH + lcolB;
    const uint32_t bBase = sb + 20480 + (wn * 64 + lrow) * PITCH + lcolB;

    float acc[2][8][4];
    #pragma unroll
    for (int i = 0; i < 2; i++)
        #pragma unroll
        for (int j = 0; j < 8; j++)
            #pragma unroll
            for (int q = 0; q < 4; q++) acc[i][j][q] = 0.0f;

    const int nk = K / 32;

    auto load_stage = [&](int ks, int buf) {
        uint32_t dst0 = sb + buf * STAGE_B;
        int k0 = ks * 32;
        if (TERMS == 3) {
            #pragma unroll
            for (int it = 0; it < 8; it++) {
                int cid = it * 256 + tid;
                int mat = cid >> 9, w = cid & 511;
                int r = w >> 2, c = w & 3;
                uint32_t dst = dst0 + mat * 10240 + r * PITCH + c * 16;
                const __nv_bfloat16* src =
                    (mat < 2 ? srcA[mat] : srcB[mat - 2]) + (size_t)r * K + k0 + c * 8;
                CP_ASYNC16(dst, src);
            }
        } else {
            #pragma unroll
            for (int it = 0; it < 4; it++) {
                int cid = it * 256 + tid;
                int isB = cid >> 9, w = cid & 511;
                int r = w >> 2, c = w & 3;
                uint32_t dst = dst0 + isB * 20480 + r * PITCH + c * 16;
                const __nv_bfloat16* src =
                    (isB ? srcB[0] : srcA[0]) + (size_t)r * K + k0 + c * 8;
                CP_ASYNC16(dst, src);
            }
        }
    };

    load_stage(0, 0); CP_COMMIT();
    load_stage(1, 1); CP_COMMIT();

    for (int ks = 0; ks < nk; ks++) {
        CP_WAIT1();
        __syncthreads();
        uint32_t bo = (ks & 1) * STAGE_B;
        #pragma unroll
        for (int kk = 0; kk < 2; kk++) {
            uint32_t ko = kk * 32;
            uint32_t ah[2][4], al[2][4], b[4][4];
            #pragma unroll
            for (int mi = 0; mi < 2; mi++) {
                ldsm4(ah[mi], aBase + bo + mi * 1280 + ko);
                if (TERMS == 3) ldsm4(al[mi], aBase + bo + 10240 + mi * 1280 + ko);
            }
            #pragma unroll
            for (int t = 0; t < 4; t++)
                ldsm4(b[t], bBase + bo + t * 1280 + ko);
            #pragma unroll
            for (int mi = 0; mi < 2; mi++)
                #pragma unroll
                for (int t = 0; t < 4; t++) {
                    mma16816(acc[mi][2*t+0], ah[mi], b[t][0], b[t][2]);
                    mma16816(acc[mi][2*t+1], ah[mi], b[t][1], b[t][3]);
                    if (TERMS == 3) {
                        mma16816(acc[mi][2*t+0], al[mi], b[t][0], b[t][2]);
                        mma16816(acc[mi][2*t+1], al[mi], b[t][1], b[t][3]);
                    }
                }
            if (TERMS == 3) {
                #pragma unroll
                for (int t = 0; t < 4; t++)
                    ldsm4(b[t], bBase + bo + 10240 + t * 1280 + ko);
                #pragma unroll
                for (int mi = 0; mi < 2; mi++)
                    #pragma unroll
                    for (int t = 0; t < 4; t++) {
                        mma16816(acc[mi][2*t+0], ah[mi], b[t][0], b[t][2]);
                        mma16816(acc[mi][2*t+1], ah[mi], b[t][1], b[t][3]);
                    }
            }
        }
        __syncthreads();
        if (ks + 2 < nk) load_stage(ks + 2, ks & 1);
        CP_COMMIT();
    }

    // epilogue
    #pragma unroll
    for (int mi = 0; mi < 2; mi++) {
        #pragma unroll
        for (int j = 0; j < 8; j++) {
            int row = m0 + wm * 32 + mi * 16 + (L >> 2);
            int col = n0 + wn * 64 + j * 8 + (L & 3) * 2;
            float v0 = acc[mi][j][0], v1 = acc[mi][j][1];
            float v2 = acc[mi][j][2], v3 = acc[mi][j][3];
            if (EPI == 1) {
                v0 = isfinite(v0) ? v0 : 0.0f; v1 = isfinite(v1) ? v1 : 0.0f;
                v2 = isfinite(v2) ? v2 : 0.0f; v3 = isfinite(v3) ? v3 : 0.0f;
            }
            if (EPI == 3) {
                float b0 = bias2[col], b1 = bias2[col + 1];
                v0 += b0; v1 += b1; v2 += b0; v3 += b1;
            }
            if (EPI == 2) {
                if (col + 1 < ldc) {
                    *reinterpret_cast<float2*>(C + (size_t)row * ldc + col)       = make_float2(v0, v1);
                    *reinterpret_cast<float2*>(C + (size_t)(row + 8) * ldc + col) = make_float2(v2, v3);
                }
            } else {
                *reinterpret_cast<float2*>(C + (size_t)row * ldc + col)       = make_float2(v0, v1);
                *reinterpret_cast<float2*>(C + (size_t)(row + 8) * ldc + col) = make_float2(v2, v3);
            }
        }
    }
}

// ---------------- SIMT GEMM (dt_proj: K=32, softplus, bf16 residual output) -----
__global__ __launch_bounds__(256)
void dtproj_kernel(const float* __restrict__ A,
                   const float* __restrict__ B,
                   const float* __restrict__ bias,
                   __nv_bfloat16* __restrict__ Chi)
{
    __shared__ float As[8][128];
    __shared__ float Bs[8][128];
    const int tid = threadIdx.x;
    const int m0 = blockIdx.y * 128, n0 = blockIdx.x * 128;
    const int tr = tid / 16, tc = tid % 16;
    const int K = 32, N = 512, lda = 36;

    float acc[8][8];
    #pragma unroll
    for (int i = 0; i < 8; i++)
        #pragma unroll
        for (int j = 0; j < 8; j++) acc[i][j] = 0.0f;

    for (int k0 = 0; k0 < K; k0 += 8) {
        {
            int row = tid >> 1, kq = (tid & 1) * 4;
            float4 v = *reinterpret_cast<const float4*>(A + (size_t)(m0 + row) * lda + k0 + kq);
            As[kq+0][row] = v.x; As[kq+1][row] = v.y; As[kq+2][row] = v.z; As[kq+3][row] = v.w;
        }
        {
            int row = tid >> 1, kq = (tid & 1) * 4;
            float4 v = *reinterpret_cast<const float4*>(B + (size_t)(n0 + row) * K + k0 + kq);
            Bs[kq+0][row] = v.x; Bs[kq+1][row] = v.y; Bs[kq+2][row] = v.z; Bs[kq+3][row] = v.w;
        }
        __syncthreads();
        #pragma unroll
        for (int k = 0; k < 8; k++) {
            float ra[8], rb[8];
            *reinterpret_cast<float4*>(&ra[0]) = *reinterpret_cast<const float4*>(&As[k][tr*8]);
            *reinterpret_cast<float4*>(&ra[4]) = *reinterpret_cast<const float4*>(&As[k][tr*8+4]);
            *reinterpret_cast<float4*>(&rb[0]) = *reinterpret_cast<const float4*>(&Bs[k][tc*8]);
            *reinterpret_cast<float4*>(&rb[4]) = *reinterpret_cast<const float4*>(&Bs[k][tc*8+4]);
            #pragma unroll
            for (int i = 0; i < 8; i++)
                #pragma unroll
                for (int j = 0; j < 8; j++)
                    acc[i][j] = fmaf(ra[i], rb[j], acc[i][j]);
        }
        __syncthreads();
    }
    #pragma unroll
    for (int i = 0; i < 8; i++) {
        size_t m = (size_t)(m0 + tr * 8 + i);
        __nv_bfloat16 ho[8];
        #pragma unroll
        for (int j = 0; j < 8; j++) {
            float v = softplusf(acc[i][j] + bias[n0 + tc * 8 + j]) - C_LN2;
            ho[j] = __float2bfloat16(v);
        }
        *reinterpret_cast<uint4*>(Chi + m * N + n0 + tc * 8) = *reinterpret_cast<uint4*>(ho);
    }
}

// ---------------- depthwise conv + silu: 4 timesteps x 4 channels per thread -----
__global__ __launch_bounds__(256)
void conv_silu_kernel(const float* __restrict__ cw, const float* __restrict__ cb)
{
    int g = blockIdx.x * 256 + threadIdx.x;    // over (SEQ/4) * 128
    int t0 = (g >> 7) * 4;
    int d4 = (g & 127) * 4;
    const float* base = g_xr + d4;

    float4 row[7];
    #pragma unroll
    for (int k = 0; k < 7; k++) {
        int t = t0 - 3 + k;
        row[k] = (t >= 0) ? *reinterpret_cast<const float4*>(base + (size_t)t * 1024)
                          : make_float4(0.f, 0.f, 0.f, 0.f);
    }
    float4 bv = *reinterpret_cast<const float4*>(cb + d4);
    const float* bb = &bv.x;
    float4 w[4];
    #pragma unroll
    for (int j = 0; j < 4; j++) w[j] = reinterpret_cast<const float4*>(cw)[d4 + j];

    #pragma unroll
    for (int i = 0; i < 4; i++) {
        float u[4];
        #pragma unroll
        for (int j = 0; j < 4; j++) {
            float a = bb[j];
            a = fmaf(w[j].x, (&row[i+0].x)[j], a);
            a = fmaf(w[j].y, (&row[i+1].x)[j], a);
            a = fmaf(w[j].z, (&row[i+2].x)[j], a);
            a = fmaf(w[j].w, (&row[i+3].x)[j], a);
            u[j] = siluf(a);
        }
        size_t o = (size_t)(t0 + i) * 512 + d4;
        *reinterpret_cast<float4*>(g_u + o) = make_float4(u[0], u[1], u[2], u[3]);
        __nv_bfloat16 h[4], l[4];
        #pragma unroll
        for (int j = 0; j < 4; j++) split_bf16(u[j], h[j], l[j]);
        *reinterpret_cast<uint2*>(g_uh + o) = *reinterpret_cast<uint2*>(h);
        *reinterpret_cast<uint2*>(g_ul + o) = *reinterpret_cast<uint2*>(l);
    }
}

// ---------------- scan passes (TCH=64, thread = 4 channels) ----------------------
__global__ __launch_bounds__(128)
void scanA_kernel(const float* __restrict__ Alog)
{
    int c  = blockIdx.x;
    int d4 = threadIdx.x * 4;
    float A0[4], A1[4], P0[4], P1[4], S0[4], S1[4];
    #pragma unroll
    for (int j = 0; j < 4; j++) {
        A0[j] = -expf(Alog[(d4 + j) * 2 + 0]);
        A1[j] = -expf(Alog[(d4 + j) * 2 + 1]);
        P0[j] = 1.f; P1[j] = 1.f; S0[j] = 0.f; S1[j] = 0.f;
    }
    const float* dp = g_dp + (size_t)c * TCH * DM + d4;
    const float* uu = g_u  + (size_t)c * TCH * DM + d4;
    const float* xd = g_xdbl + (size_t)c * TCH * 36;
    #pragma unroll 4
    for (int i = 0; i < TCH; i++) {
        float4 dpv = *reinterpret_cast<const float4*>(dp + (size_t)i * DM);
        float4 uv  = *reinterpret_cast<const float4*>(uu + (size_t)i * DM);
        float B0 = xd[i * 36 + 32], B1 = xd[i * 36 + 33];
        const float* dj = &dpv.x; const float* uj = &uv.x;
        #pragma unroll
        for (int j = 0; j < 4; j++) {
            float x0 = dj[j] * A0[j], x1 = dj[j] * A1[j];
            float a0 = 0.f, a1 = 0.f;
            if (fmaxf(x0, x1) > -87.0f) { a0 = __expf(x0); a1 = __expf(x1); }
            float bu = dj[j] * uj[j];
            S0[j] = fmaf(a0, S0[j], bu * B0);
            S1[j] = fmaf(a1, S1[j], bu * B1);
            P0[j] *= a0; P1[j] *= a1;
        }
    }
    #pragma unroll
    for (int j = 0; j < 4; j++) {
        int dn = (d4 + j) * 2;
        g_P[c * 1024 + dn] = P0[j]; g_P[c * 1024 + dn + 1] = P1[j];
        g_S[c * 1024 + dn] = S0[j]; g_S[c * 1024 + dn + 1] = S1[j];
    }
}

__global__ __launch_bounds__(128)
void scanB_kernel()
{
    int dn = blockIdx.x * 128 + threadIdx.x;
    float h = 0.0f;
    for (int cb = 0; cb < NCH; cb += 16) {
        float p[16], s[16];
        #pragma unroll
        for (int i = 0; i < 16; i++) {
            p[i] = g_P[(cb + i) * 1024 + dn];
            s[i] = g_S[(cb + i) * 1024 + dn];
        }
        #pragma unroll
        for (int i = 0; i < 16; i++) {
            g_H[(cb + i) * 1024 + dn] = h;
            h = fmaf(p[i], h, s[i]);
        }
    }
}

__global__ __launch_bounds__(128)
void scanC_kernel(const float* __restrict__ Alog, const float* __restrict__ Dw)
{
    int c  = blockIdx.x;
    int d4 = threadIdx.x * 4;
    float A0[4], A1[4], h0[4], h1[4];
    #pragma unroll
    for (int j = 0; j < 4; j++) {
        A0[j] = -expf(Alog[(d4 + j) * 2 + 0]);
        A1[j] = -expf(Alog[(d4 + j) * 2 + 1]);
        h0[j] = g_H[c * 1024 + (d4 + j) * 2];
        h1[j] = g_H[c * 1024 + (d4 + j) * 2 + 1];
    }
    float4 Dv4 = *reinterpret_cast<const float4*>(Dw + d4);
    const float* Dv = &Dv4.x;
    const float* dp = g_dp + (size_t)c * TCH * DM + d4;
    const float* uu = g_u  + (size_t)c * TCH * DM + d4;
    const float* xd = g_xdbl + (size_t)c * TCH * 36;
    const float* rs = g_xr + (size_t)c * TCH * 1024 + 512 + d4;
    __nv_bfloat16* yh = g_yh + (size_t)c * TCH * DM + d4;
    __nv_bfloat16* yl = g_yl + (size_t)c * TCH * DM + d4;
    #pragma unroll 4
    for (int i = 0; i < TCH; i++) {
        float4 dpv = *reinterpret_cast<const float4*>(dp + (size_t)i * DM);
        float4 uv  = *reinterpret_cast<const float4*>(uu + (size_t)i * DM);
        float4 rv  = *reinterpret_cast<const float4*>(rs + (size_t)i * 1024);
        float B0 = xd[i * 36 + 32], B1 = xd[i * 36 + 33];
        float C0 = xd[i * 36 + 34], C1 = xd[i * 36 + 35];
        const float* dj = &dpv.x; const float* uj = &uv.x; const float* rj = &rv.x;
        __nv_bfloat16 oh[4], ol[4];
        #pragma unroll
        for (int j = 0; j < 4; j++) {
            float x0 = dj[j] * A0[j], x1 = dj[j] * A1[j];
            float a0 = 0.f, a1 = 0.f;
            if (fmaxf(x0, x1) > -87.0f) { a0 = __expf(x0); a1 = __expf(x1); }
            float bu = dj[j] * uj[j];
            h0[j] = fmaf(a0, h0[j], bu * B0);
            h1[j] = fmaf(a1, h1[j], bu * B1);
            float y = fmaf(h0[j], C0, fmaf(h1[j], C1, uj[j] * Dv[j]));
            y *= siluf(rj[j]);
            split_bf16(y, oh[j], ol[j]);
        }
        *reinterpret_cast<uint2*>(yh + (size_t)i * DM) = *reinterpret_cast<uint2*>(oh);
        *reinterpret_cast<uint2*>(yl + (size_t)i * DM) = *reinterpret_cast<uint2*>(ol);
    }
}

// ---------------- launch --------------------------------------------------------
extern "C" void kernel_launch(void* const* d_in, const int* in_sizes, int n_in,
                              void* d_out, int out_size)
{
    const float* x     = (const float*)d_in[0];
    const float* dis   = (const float*)d_in[1];
    const float* inw   = (const float*)d_in[2];
    const float* convw = (const float*)d_in[3];
    const float* convb = (const float*)d_in[4];
    const float* xpw   = (const float*)d_in[5];
    const float* dtw   = (const float*)d_in[6];
    const float* dtb   = (const float*)d_in[7];
    const float* alog  = (const float*)d_in[8];
    const float* Dw    = (const float*)d_in[9];
    const float* outw  = (const float*)d_in[10];
    float* out = (float*)d_out;

    float *xr, *dp, *xdbl, *csum;
    __nv_bfloat16 *xh, *xl, *uh, *ul, *dh, *yh, *yl;
    __nv_bfloat16 *wih, *wil, *dsh, *dsl, *woh, *wol, *xph, *xpl;
    cudaGetSymbolAddress((void**)&xr,   g_xr);
    cudaGetSymbolAddress((void**)&dp,   g_dp);
    cudaGetSymbolAddress((void**)&xdbl, g_xdbl);
    cudaGetSymbolAddress((void**)&csum, g_csum);
    cudaGetSymbolAddress((void**)&xh,  g_xh);  cudaGetSymbolAddress((void**)&xl,  g_xl);
    cudaGetSymbolAddress((void**)&uh,  g_uh);  cudaGetSymbolAddress((void**)&ul,  g_ul);
    cudaGetSymbolAddress((void**)&dh,  g_dh);
    cudaGetSymbolAddress((void**)&yh,  g_yh);  cudaGetSymbolAddress((void**)&yl,  g_yl);
    cudaGetSymbolAddress((void**)&wih, g_wih); cudaGetSymbolAddress((void**)&wil, g_wil);
    cudaGetSymbolAddress((void**)&dsh, g_dsh); cudaGetSymbolAddress((void**)&dsl, g_dsl);
    cudaGetSymbolAddress((void**)&woh, g_woh); cudaGetSymbolAddress((void**)&wol, g_wol);
    cudaGetSymbolAddress((void**)&xph, g_xph); cudaGetSymbolAddress((void**)&xpl, g_xpl);

    const int GEMM_SMEM = 2 * STAGE_B;   // 81920
    cudaFuncSetAttribute((const void*)mma_gemm<0,3>, cudaFuncAttributeMaxDynamicSharedMemorySize, GEMM_SMEM);
    cudaFuncSetAttribute((const void*)mma_gemm<1,3>, cudaFuncAttributeMaxDynamicSharedMemorySize, GEMM_SMEM);
    cudaFuncSetAttribute((const void*)mma_gemm<2,3>, cudaFuncAttributeMaxDynamicSharedMemorySize, GEMM_SMEM);
    cudaFuncSetAttribute((const void*)mma_gemm<3,1>, cudaFuncAttributeMaxDynamicSharedMemorySize, GEMM_SMEM);

    // 0) all split conversions + dis colsum
    cvt_all<<<18432, 256>>>(x, inw, outw, dis, xpw);
    colsum_kernel<<<2, 256>>>(dis);

    // 1) xr = x @ in_proj_w^T   [32768 x 1024]
    mma_gemm<0,3><<<dim3(8, SEQ / 128), 256, GEMM_SMEM>>>(xh, xl, wih, wil, xr, nullptr, 1024, 512, 1024);

    // 2) u = silu(conv(xs))  (+ bf16 split), 4 timesteps/thread
    conv_silu_kernel<<<(SEQ / 4 * 128) / 256, 256>>>(convw, convb);

    // 3) xdbl = u @ x_proj_w^T  (N padded to 128, store cols<36)
    mma_gemm<2,3><<<dim3(1, SEQ / 128), 256, GEMM_SMEM>>>(uh, ul, xph, xpl, xdbl, nullptr, 128, 512, 36);

    // 4) delta residual = softplus(xdbl[:, :32] @ dt_proj_w^T + b) - ln2 -> bf16
    dtproj_kernel<<<dim3(DM / 128, SEQ / 128), 256>>>(g_xdbl, dtw, dtb, dh);

    // 5) delta_p = ln2*colsum(dis) + residual @ dis
    mma_gemm<3,1><<<dim3(DM / 128, SEQ / 128), 256, GEMM_SMEM>>>(dh, nullptr, dsh, nullptr, dp, csum, DM, 512, DM);

    // 6-8) chunked selective scan
    scanA_kernel<<<NCH, 128>>>(alog);
    scanB_kernel<<<8, 128>>>();
    scanC_kernel<<<NCH, 128>>>(alog, Dw);

    // 9) out = y @ out_proj_w^T, finite filter
    mma_gemm<1,3><<<dim3(DM / 128, SEQ / 128), 256, GEMM_SMEM>>>(yh, yl, woh, wol, out, nullptr, DM, 512, DM);
}

// round 11
// speedup vs baseline: 1.7283x; 1.1217x over previous
#include <cuda_runtime.h>
#include <cuda_bf16.h>
#include <math.h>
#include <stdint.h>

#define SEQ   32768
#define DM    512
#define NCH   512
#define TCH   64
#define C_LN2 0.69314718055994531f

// ---------------- scratch (device globals) -----------------------------------
__device__ float g_xr  [(size_t)SEQ * 1024];
__device__ float g_u   [(size_t)SEQ * DM];
__device__ float g_xdbl[(size_t)SEQ * 36];
__device__ float g_dp  [(size_t)SEQ * DM];
__device__ float g_P   [NCH * 1024];
__device__ float g_S   [NCH * 1024];
__device__ float g_H   [NCH * 1024];
__device__ float g_csum[DM];

__device__ __nv_bfloat16 g_xh [(size_t)SEQ * DM], g_xl [(size_t)SEQ * DM];
__device__ __nv_bfloat16 g_uh [(size_t)SEQ * DM], g_ul [(size_t)SEQ * DM];
__device__ __nv_bfloat16 g_dh [(size_t)SEQ * DM];
__device__ __nv_bfloat16 g_yh [(size_t)SEQ * DM], g_yl [(size_t)SEQ * DM];
__device__ __nv_bfloat16 g_xbh[(size_t)SEQ * 32];                 // xdbl cols 0..31 bf16
__device__ __nv_bfloat16 g_wih[1024 * 512],       g_wil[1024 * 512];
__device__ __nv_bfloat16 g_dsh[512 * 512];
__device__ __nv_bfloat16 g_woh[512 * 512],        g_wol[512 * 512];
__device__ __nv_bfloat16 g_xph[128 * 512],        g_xpl[128 * 512];
__device__ __nv_bfloat16 g_dtwh[512 * 32];                        // dt_proj_w bf16

// ---------------- PTX helpers ---------------------------------------------------
__device__ __forceinline__ uint32_t smem_u32(const void* p) {
    uint32_t a;
    asm("{ .reg .u64 t; cvta.to.shared.u64 t, %1; cvt.u32.u64 %0, t; }" : "=r"(a) : "l"(p));
    return a;
}
#define CP_ASYNC16(dst, src) \
    asm volatile("cp.async.cg.shared.global [%0], [%1], 16;" :: "r"(dst), "l"(src) : "memory")
#define CP_COMMIT() asm volatile("cp.async.commit_group;" ::: "memory")
#define CP_WAIT1()  asm volatile("cp.async.wait_group 1;" ::: "memory")
#define CP_WAIT0()  asm volatile("cp.async.wait_group 0;" ::: "memory")

__device__ __forceinline__ void ldsm4(uint32_t* r, uint32_t addr) {
    asm volatile("ldmatrix.sync.aligned.m8n8.x4.shared.b16 {%0,%1,%2,%3}, [%4];"
                 : "=r"(r[0]), "=r"(r[1]), "=r"(r[2]), "=r"(r[3]) : "r"(addr));
}
__device__ __forceinline__ void mma16816(float* c, const uint32_t* a,
                                         uint32_t b0, uint32_t b1) {
    asm volatile("mma.sync.aligned.m16n8k16.row.col.f32.bf16.bf16.f32 "
                 "{%0,%1,%2,%3}, {%4,%5,%6,%7}, {%8,%9}, {%0,%1,%2,%3};"
                 : "+f"(c[0]), "+f"(c[1]), "+f"(c[2]), "+f"(c[3])
                 : "r"(a[0]), "r"(a[1]), "r"(a[2]), "r"(a[3]), "r"(b0), "r"(b1));
}

// ---------------- math helpers --------------------------------------------------
__device__ __forceinline__ float softplusf(float x) {
    float ax = fabsf(x);
    if (ax < 0.25f) {
        float x2 = x * x;
        return C_LN2 + 0.5f * x
             + x2 * (0.125f + x2 * (-1.0f/192.0f + x2 * (1.0f/2880.0f)));
    }
    return fmaxf(x, 0.0f) + log1pf(expf(-ax));
}
__device__ __forceinline__ float siluf(float x) { return x / (1.0f + __expf(-x)); }
__device__ __forceinline__ void split_bf16(float v, __nv_bfloat16& h, __nv_bfloat16& l) {
    h = __float2bfloat16(v);
    l = __float2bfloat16(v - __bfloat162float(h));
}

// ---------------- combined split conversion kernel ------------------------------
// seg0 x:16384  seg1 inw:512  seg2 outw:256  seg3 dis^T:1024  seg4 xpw:256
// seg5 dtw->bf16: 16 blocks (float4)   seg6 colsum: 2 blocks
__global__ __launch_bounds__(256)
void cvt_all(const float* __restrict__ x, const float* __restrict__ inw,
             const float* __restrict__ outw, const float* __restrict__ dis,
             const float* __restrict__ xpw, const float* __restrict__ dtw)
{
    int b = blockIdx.x;
    if (b < 16384) {
        int i = b * 256 + threadIdx.x;
        float4 v = reinterpret_cast<const float4*>(x)[i];
        __nv_bfloat16 h[4], l[4];
        split_bf16(v.x, h[0], l[0]); split_bf16(v.y, h[1], l[1]);
        split_bf16(v.z, h[2], l[2]); split_bf16(v.w, h[3], l[3]);
        reinterpret_cast<uint2*>(g_xh)[i] = *reinterpret_cast<uint2*>(h);
        reinterpret_cast<uint2*>(g_xl)[i] = *reinterpret_cast<uint2*>(l);
    } else if (b < 16896) {
        int i = (b - 16384) * 256 + threadIdx.x;
        float4 v = reinterpret_cast<const float4*>(inw)[i];
        __nv_bfloat16 h[4], l[4];
        split_bf16(v.x, h[0], l[0]); split_bf16(v.y, h[1], l[1]);
        split_bf16(v.z, h[2], l[2]); split_bf16(v.w, h[3], l[3]);
        reinterpret_cast<uint2*>(g_wih)[i] = *reinterpret_cast<uint2*>(h);
        reinterpret_cast<uint2*>(g_wil)[i] = *reinterpret_cast<uint2*>(l);
    } else if (b < 17152) {
        int i = (b - 16896) * 256 + threadIdx.x;
        float4 v = reinterpret_cast<const float4*>(outw)[i];
        __nv_bfloat16 h[4], l[4];
        split_bf16(v.x, h[0], l[0]); split_bf16(v.y, h[1], l[1]);
        split_bf16(v.z, h[2], l[2]); split_bf16(v.w, h[3], l[3]);
        reinterpret_cast<uint2*>(g_woh)[i] = *reinterpret_cast<uint2*>(h);
        reinterpret_cast<uint2*>(g_wol)[i] = *reinterpret_cast<uint2*>(l);
    } else if (b < 18176) {
        int idx = (b - 17152) * 256 + threadIdx.x;
        int n = idx >> 9, k = idx & 511;
        g_dsh[idx] = __float2bfloat16(dis[k * 512 + n]);
    } else if (b < 18432) {
        int idx = (b - 18176) * 256 + threadIdx.x;   // 128x512 padded
        int r = idx >> 9;
        __nv_bfloat16 h = __float2bfloat16(0.0f), l = h;
        if (r < 36) split_bf16(xpw[idx], h, l);
        g_xph[idx] = h; g_xpl[idx] = l;
    } else if (b < 18448) {
        int i = (b - 18432) * 256 + threadIdx.x;     // 512*32/4 = 4096 float4
        float4 v = reinterpret_cast<const float4*>(dtw)[i];
        __nv_bfloat16 h[4];
        h[0] = __float2bfloat16(v.x); h[1] = __float2bfloat16(v.y);
        h[2] = __float2bfloat16(v.z); h[3] = __float2bfloat16(v.w);
        reinterpret_cast<uint2*>(g_dtwh)[i] = *reinterpret_cast<uint2*>(h);
    } else {
        int n = (b - 18448) * 256 + threadIdx.x;     // colsum, 2 blocks
        float s = 0.0f;
        #pragma unroll 8
        for (int k = 0; k < 512; k++) s += dis[k * 512 + n];
        g_csum[n] = s * C_LN2;
    }
}

// ---------------- mma.sync bf16 GEMM (R8 mainloop, BN-templated) -----------------
// TERMS=3: C = (Ah+Al)@(Bh+Bl)^T.  TERMS=1: C = Ah@Bh^T (BN must be 128).
// CTA 128m x BNn, 256 threads (8 warps, 4m x 2n), warp tile 32 x BN/2, BK=32, 2 stages.
// EPI: 0 plain, 1 finite filter, 2 narrow store (cols<ldc fp32 + cols<32 bf16->g_xbh),
//      3 += bias2[col]
#define PITCH   80
template <int EPI, int TERMS, int BN>
__global__ __launch_bounds__(256, 2)
void mma_gemm(const __nv_bfloat16* __restrict__ Ah, const __nv_bfloat16* __restrict__ Al,
              const __nv_bfloat16* __restrict__ Bh, const __nv_bfloat16* __restrict__ Bl,
              float* __restrict__ C, const float* __restrict__ bias2,
              int N, int K, int ldc)
{
    constexpr int WN = BN / 2;          // warp n-extent: 64 or 32
    constexpr int TB = WN / 16;         // b-ldsm per warp: 4 or 2
    constexpr uint32_t STAGE = 20480 + 2 * BN * PITCH;

    extern __shared__ char dsm[];
    const uint32_t sb = smem_u32(dsm);
    const int tid = threadIdx.x;
    const int wid = tid >> 5, L = tid & 31;
    const int wm = wid >> 1, wn = wid & 1;
    const int m0 = blockIdx.y * 128, n0 = blockIdx.x * BN;

    const __nv_bfloat16* srcA[2] = { Ah + (size_t)m0 * K,
                                     (TERMS == 3 ? Al : Ah) + (size_t)m0 * K };
    const __nv_bfloat16* srcB[2] = { Bh + (size_t)n0 * K,
                                     (TERMS == 3 ? Bl : Bh) + (size_t)n0 * K };

    const int lrow = L & 15;
    const int lcolB = (L >> 4) * 16;
    const uint32_t aBase = sb + (wm * 32 + lrow) * PITCH + lcolB;
    const uint32_t bBase = sb + 20480 + (wn * WN + lrow) * PITCH + lcolB;

    float acc[2][2 * TB][4];
    #pragma unroll
    for (int i = 0; i < 2; i++)
        #pragma unroll
        for (int j = 0; j < 2 * TB; j++)
            #pragma unroll
            for (int q = 0; q < 4; q++) acc[i][j][q] = 0.0f;

    const int nk = K / 32;

    auto load_stage = [&](int ks, int buf) {
        uint32_t dst0 = sb + buf * STAGE;
        int k0 = ks * 32;
        if (TERMS == 3) {
            constexpr int ITERS = (1024 + 8 * BN) / 256;
            #pragma unroll
            for (int it = 0; it < ITERS; it++) {
                int cid = it * 256 + tid;
                if (cid < 1024) {
                    int mat = cid >> 9, w = cid & 511;
                    int r = w >> 2, c = w & 3;
                    uint32_t dst = dst0 + mat * 10240 + r * PITCH + c * 16;
                    CP_ASYNC16(dst, srcA[mat] + (size_t)r * K + k0 + c * 8);
                } else {
                    int w2 = cid - 1024;
                    int matB = w2 / (BN * 4);
                    int rw = w2 - matB * BN * 4;
                    int r = rw >> 2, c = rw & 3;
                    uint32_t dst = dst0 + 20480 + matB * (BN * PITCH) + r * PITCH + c * 16;
                    CP_ASYNC16(dst, srcB[matB] + (size_t)r * K + k0 + c * 8);
                }
            }
        } else {
            #pragma unroll
            for (int it = 0; it < 4; it++) {
                int cid = it * 256 + tid;
                int isB = cid >> 9, w = cid & 511;
                int r = w >> 2, c = w & 3;
                uint32_t dst = dst0 + isB * 20480 + r * PITCH + c * 16;
                const __nv_bfloat16* src =
                    (isB ? srcB[0] : srcA[0]) + (size_t)r * K + k0 + c * 8;
                CP_ASYNC16(dst, src);
            }
        }
    };

    load_stage(0, 0); CP_COMMIT();
    load_stage(1, 1); CP_COMMIT();

    for (int ks = 0; ks < nk; ks++) {
        CP_WAIT1();
        __syncthreads();
        uint32_t bo = (ks & 1) * STAGE;
        #pragma unroll
        for (int kk = 0; kk < 2; kk++) {
            uint32_t ko = kk * 32;
            uint32_t ah[2][4], al[2][4], b[TB][4];
            #pragma unroll
            for (int mi = 0; mi < 2; mi++) {
                ldsm4(ah[mi], aBase + bo + mi * 1280 + ko);
                if (TERMS == 3) ldsm4(al[mi], aBase + bo + 10240 + mi * 1280 + ko);
            }
            #pragma unroll
            for (int t = 0; t < TB; t++)
                ldsm4(b[t], bBase + bo + t * 1280 + ko);
            #pragma unroll
            for (int mi = 0; mi < 2; mi++)
                #pragma unroll
                for (int t = 0; t < TB; t++) {
                    mma16816(acc[mi][2*t+0], ah[mi], b[t][0], b[t][2]);
                    mma16816(acc[mi][2*t+1], ah[mi], b[t][1], b[t][3]);
                    if (TERMS == 3) {
                        mma16816(acc[mi][2*t+0], al[mi], b[t][0], b[t][2]);
                        mma16816(acc[mi][2*t+1], al[mi], b[t][1], b[t][3]);
                    }
                }
            if (TERMS == 3) {
                #pragma unroll
                for (int t = 0; t < TB; t++)
                    ldsm4(b[t], bBase + bo + BN * PITCH + t * 1280 + ko);
                #pragma unroll
                for (int mi = 0; mi < 2; mi++)
                    #pragma unroll
                    for (int t = 0; t < TB; t++) {
                        mma16816(acc[mi][2*t+0], ah[mi], b[t][0], b[t][2]);
                        mma16816(acc[mi][2*t+1], ah[mi], b[t][1], b[t][3]);
                    }
            }
        }
        __syncthreads();
        if (ks + 2 < nk) load_stage(ks + 2, ks & 1);
        CP_COMMIT();
    }

    // epilogue
    #pragma unroll
    for (int mi = 0; mi < 2; mi++) {
        #pragma unroll
        for (int j = 0; j < 2 * TB; j++) {
            int row = m0 + wm * 32 + mi * 16 + (L >> 2);
            int col = n0 + wn * WN + j * 8 + (L & 3) * 2;
            float v0 = acc[mi][j][0], v1 = acc[mi][j][1];
            float v2 = acc[mi][j][2], v3 = acc[mi][j][3];
            if (EPI == 1) {
                v0 = isfinite(v0) ? v0 : 0.0f; v1 = isfinite(v1) ? v1 : 0.0f;
                v2 = isfinite(v2) ? v2 : 0.0f; v3 = isfinite(v3) ? v3 : 0.0f;
            }
            if (EPI == 3) {
                float b0 = bias2[col], b1 = bias2[col + 1];
                v0 += b0; v1 += b1; v2 += b0; v3 += b1;
            }
            if (EPI == 2) {
                if (col + 1 < ldc) {
                    *reinterpret_cast<float2*>(C + (size_t)row * ldc + col)       = make_float2(v0, v1);
                    *reinterpret_cast<float2*>(C + (size_t)(row + 8) * ldc + col) = make_float2(v2, v3);
                }
                if (col + 1 < 32) {
                    __nv_bfloat16 p0[2] = { __float2bfloat16(v0), __float2bfloat16(v1) };
                    __nv_bfloat16 p1[2] = { __float2bfloat16(v2), __float2bfloat16(v3) };
                    *reinterpret_cast<uint32_t*>(g_xbh + (size_t)row * 32 + col)       = *reinterpret_cast<uint32_t*>(p0);
                    *reinterpret_cast<uint32_t*>(g_xbh + (size_t)(row + 8) * 32 + col) = *reinterpret_cast<uint32_t*>(p1);
                }
            } else {
                *reinterpret_cast<float2*>(C + (size_t)row * ldc + col)       = make_float2(v0, v1);
                *reinterpret_cast<float2*>(C + (size_t)(row + 8) * ldc + col) = make_float2(v2, v3);
            }
        }
    }
}

// ---------------- dtproj via tensor cores (K=32, single stage) -------------------
// delta_res[m, n] = softplus(xbh[m,:32] @ dtwh[n,:32]^T + dtb[n]) - ln2 -> bf16
__global__ __launch_bounds__(256)
void dtproj_mma(const float* __restrict__ dtb)
{
    extern __shared__ char dsm[];
    const uint32_t sb = smem_u32(dsm);
    const int tid = threadIdx.x;
    const int wid = tid >> 5, L = tid & 31;
    const int wm = wid >> 1, wn = wid & 1;
    const int m0 = blockIdx.y * 128, n0 = blockIdx.x * 128;

    // load A (g_xbh rows m0..m0+127, 64B each) and B (g_dtwh rows n0..n0+127)
    {
        #pragma unroll
        for (int it = 0; it < 4; it++) {
            int cid = it * 256 + tid;
            int isB = cid >> 9, w = cid & 511;
            int r = w >> 2, c = w & 3;
            uint32_t dst = sb + isB * 10240 + r * PITCH + c * 16;
            const __nv_bfloat16* src = isB ? (g_dtwh + (size_t)(n0 + r) * 32 + c * 8)
                                           : (g_xbh + (size_t)(m0 + r) * 32 + c * 8);
            CP_ASYNC16(dst, src);
        }
    }
    CP_COMMIT();
    CP_WAIT0();
    __syncthreads();

    const int lrow = L & 15;
    const int lcolB = (L >> 4) * 16;
    const uint32_t aBase = sb + (wm * 32 + lrow) * PITCH + lcolB;
    const uint32_t bBase = sb + 10240 + (wn * 64 + lrow) * PITCH + lcolB;

    float acc[2][8][4];
    #pragma unroll
    for (int i = 0; i < 2; i++)
        #pragma unroll
        for (int j = 0; j < 8; j++)
            #pragma unroll
            for (int q = 0; q < 4; q++) acc[i][j][q] = 0.0f;

    #pragma unroll
    for (int kk = 0; kk < 2; kk++) {
        uint32_t ko = kk * 32;
        uint32_t ah[2][4], b[4][4];
        #pragma unroll
        for (int mi = 0; mi < 2; mi++)
            ldsm4(ah[mi], aBase + mi * 1280 + ko);
        #pragma unroll
        for (int t = 0; t < 4; t++)
            ldsm4(b[t], bBase + t * 1280 + ko);
        #pragma unroll
        for (int mi = 0; mi < 2; mi++)
            #pragma unroll
            for (int t = 0; t < 4; t++) {
                mma16816(acc[mi][2*t+0], ah[mi], b[t][0], b[t][2]);
                mma16816(acc[mi][2*t+1], ah[mi], b[t][1], b[t][3]);
            }
    }

    #pragma unroll
    for (int mi = 0; mi < 2; mi++) {
        #pragma unroll
        for (int j = 0; j < 8; j++) {
            int row = m0 + wm * 32 + mi * 16 + (L >> 2);
            int col = n0 + wn * 64 + j * 8 + (L & 3) * 2;
            float b0 = dtb[col], b1 = dtb[col + 1];
            __nv_bfloat16 p0[2] = {
                __float2bfloat16(softplusf(acc[mi][j][0] + b0) - C_LN2),
                __float2bfloat16(softplusf(acc[mi][j][1] + b1) - C_LN2) };
            __nv_bfloat16 p1[2] = {
                __float2bfloat16(softplusf(acc[mi][j][2] + b0) - C_LN2),
                __float2bfloat16(softplusf(acc[mi][j][3] + b1) - C_LN2) };
            *reinterpret_cast<uint32_t*>(g_dh + (size_t)row * 512 + col)       = *reinterpret_cast<uint32_t*>(p0);
            *reinterpret_cast<uint32_t*>(g_dh + (size_t)(row + 8) * 512 + col) = *reinterpret_cast<uint32_t*>(p1);
        }
    }
}

// ---------------- depthwise conv + silu: 4 timesteps x 4 channels per thread -----
__global__ __launch_bounds__(256)
void conv_silu_kernel(const float* __restrict__ cw, const float* __restrict__ cb)
{
    int g = blockIdx.x * 256 + threadIdx.x;
    int t0 = (g >> 7) * 4;
    int d4 = (g & 127) * 4;
    const float* base = g_xr + d4;

    float4 row[7];
    #pragma unroll
    for (int k = 0; k < 7; k++) {
        int t = t0 - 3 + k;
        row[k] = (t >= 0) ? *reinterpret_cast<const float4*>(base + (size_t)t * 1024)
                          : make_float4(0.f, 0.f, 0.f, 0.f);
    }
    float4 bv = *reinterpret_cast<const float4*>(cb + d4);
    const float* bb = &bv.x;
    float4 w[4];
    #pragma unroll
    for (int j = 0; j < 4; j++) w[j] = reinterpret_cast<const float4*>(cw)[d4 + j];

    #pragma unroll
    for (int i = 0; i < 4; i++) {
        float u[4];
        #pragma unroll
        for (int j = 0; j < 4; j++) {
            float a = bb[j];
            a = fmaf(w[j].x, (&row[i+0].x)[j], a);
            a = fmaf(w[j].y, (&row[i+1].x)[j], a);
            a = fmaf(w[j].z, (&row[i+2].x)[j], a);
            a = fmaf(w[j].w, (&row[i+3].x)[j], a);
            u[j] = siluf(a);
        }
        size_t o = (size_t)(t0 + i) * 512 + d4;
        *reinterpret_cast<float4*>(g_u + o) = make_float4(u[0], u[1], u[2], u[3]);
        __nv_bfloat16 h[4], l[4];
        #pragma unroll
        for (int j = 0; j < 4; j++) split_bf16(u[j], h[j], l[j]);
        *reinterpret_cast<uint2*>(g_uh + o) = *reinterpret_cast<uint2*>(h);
        *reinterpret_cast<uint2*>(g_ul + o) = *reinterpret_cast<uint2*>(l);
    }
}

// ---------------- scan passes (TCH=64, thread = 4 channels) ----------------------
__global__ __launch_bounds__(128)
void scanA_kernel(const float* __restrict__ Alog)
{
    int c  = blockIdx.x;
    int d4 = threadIdx.x * 4;
    float A0[4], A1[4], P0[4], P1[4], S0[4], S1[4];
    #pragma unroll
    for (int j = 0; j < 4; j++) {
        A0[j] = -expf(Alog[(d4 + j) * 2 + 0]);
        A1[j] = -expf(Alog[(d4 + j) * 2 + 1]);
        P0[j] = 1.f; P1[j] = 1.f; S0[j] = 0.f; S1[j] = 0.f;
    }
    const float* dp = g_dp + (size_t)c * TCH * DM + d4;
    const float* uu = g_u  + (size_t)c * TCH * DM + d4;
    const float* xd = g_xdbl + (size_t)c * TCH * 36;
    #pragma unroll 4
    for (int i = 0; i < TCH; i++) {
        float4 dpv = *reinterpret_cast<const float4*>(dp + (size_t)i * DM);
        float4 uv  = *reinterpret_cast<const float4*>(uu + (size_t)i * DM);
        float B0 = xd[i * 36 + 32], B1 = xd[i * 36 + 33];
        const float* dj = &dpv.x; const float* uj = &uv.x;
        #pragma unroll
        for (int j = 0; j < 4; j++) {
            float x0 = dj[j] * A0[j], x1 = dj[j] * A1[j];
            float a0 = 0.f, a1 = 0.f;
            if (fmaxf(x0, x1) > -87.0f) { a0 = __expf(x0); a1 = __expf(x1); }
            float bu = dj[j] * uj[j];
            S0[j] = fmaf(a0, S0[j], bu * B0);
            S1[j] = fmaf(a1, S1[j], bu * B1);
            P0[j] *= a0; P1[j] *= a1;
        }
    }
    #pragma unroll
    for (int j = 0; j < 4; j++) {
        int dn = (d4 + j) * 2;
        g_P[c * 1024 + dn] = P0[j]; g_P[c * 1024 + dn + 1] = P1[j];
        g_S[c * 1024 + dn] = S0[j]; g_S[c * 1024 + dn + 1] = S1[j];
    }
}

__global__ __launch_bounds__(128)
void scanB_kernel()
{
    int dn = blockIdx.x * 128 + threadIdx.x;
    float h = 0.0f;
    for (int cb = 0; cb < NCH; cb += 16) {
        float p[16], s[16];
        #pragma unroll
        for (int i = 0; i < 16; i++) {
            p[i] = g_P[(cb + i) * 1024 + dn];
            s[i] = g_S[(cb + i) * 1024 + dn];
        }
        #pragma unroll
        for (int i = 0; i < 16; i++) {
            g_H[(cb + i) * 1024 + dn] = h;
            h = fmaf(p[i], h, s[i]);
        }
    }
}

__global__ __launch_bounds__(128)
void scanC_kernel(const float* __restrict__ Alog, const float* __restrict__ Dw)
{
    int c  = blockIdx.x;
    int d4 = threadIdx.x * 4;
    float A0[4], A1[4], h0[4], h1[4];
    #pragma unroll
    for (int j = 0; j < 4; j++) {
        A0[j] = -expf(Alog[(d4 + j) * 2 + 0]);
        A1[j] = -expf(Alog[(d4 + j) * 2 + 1]);
        h0[j] = g_H[c * 1024 + (d4 + j) * 2];
        h1[j] = g_H[c * 1024 + (d4 + j) * 2 + 1];
    }
    float4 Dv4 = *reinterpret_cast<const float4*>(Dw + d4);
    const float* Dv = &Dv4.x;
    const float* dp = g_dp + (size_t)c * TCH * DM + d4;
    const float* uu = g_u  + (size_t)c * TCH * DM + d4;
    const float* xd = g_xdbl + (size_t)c * TCH * 36;
    const float* rs = g_xr + (size_t)c * TCH * 1024 + 512 + d4;
    __nv_bfloat16* yh = g_yh + (size_t)c * TCH * DM + d4;
    __nv_bfloat16* yl = g_yl + (size_t)c * TCH * DM + d4;
    #pragma unroll 4
    for (int i = 0; i < TCH; i++) {
        float4 dpv = *reinterpret_cast<const float4*>(dp + (size_t)i * DM);
        float4 uv  = *reinterpret_cast<const float4*>(uu + (size_t)i * DM);
        float4 rv  = *reinterpret_cast<const float4*>(rs + (size_t)i * 1024);
        float B0 = xd[i * 36 + 32], B1 = xd[i * 36 + 33];
        float C0 = xd[i * 36 + 34], C1 = xd[i * 36 + 35];
        const float* dj = &dpv.x; const float* uj = &uv.x; const float* rj = &rv.x;
        __nv_bfloat16 oh[4], ol[4];
        #pragma unroll
        for (int j = 0; j < 4; j++) {
            float x0 = dj[j] * A0[j], x1 = dj[j] * A1[j];
            float a0 = 0.f, a1 = 0.f;
            if (fmaxf(x0, x1) > -87.0f) { a0 = __expf(x0); a1 = __expf(x1); }
            float bu = dj[j] * uj[j];
            h0[j] = fmaf(a0, h0[j], bu * B0);
            h1[j] = fmaf(a1, h1[j], bu * B1);
            float y = fmaf(h0[j], C0, fmaf(h1[j], C1, uj[j] * Dv[j]));
            y *= siluf(rj[j]);
            split_bf16(y, oh[j], ol[j]);
        }
        *reinterpret_cast<uint2*>(yh + (size_t)i * DM) = *reinterpret_cast<uint2*>(oh);
        *reinterpret_cast<uint2*>(yl + (size_t)i * DM) = *reinterpret_cast<uint2*>(ol);
    }
}

// ---------------- launch --------------------------------------------------------
extern "C" void kernel_launch(void* const* d_in, const int* in_sizes, int n_in,
                              void* d_out, int out_size)
{
    const float* x     = (const float*)d_in[0];
    const float* dis   = (const float*)d_in[1];
    const float* inw   = (const float*)d_in[2];
    const float* convw = (const float*)d_in[3];
    const float* convb = (const float*)d_in[4];
    const float* xpw   = (const float*)d_in[5];
    const float* dtw   = (const float*)d_in[6];
    const float* dtb   = (const float*)d_in[7];
    const float* alog  = (const float*)d_in[8];
    const float* Dw    = (const float*)d_in[9];
    const float* outw  = (const float*)d_in[10];
    float* out = (float*)d_out;

    float *xr, *dp, *xdbl, *csum;
    __nv_bfloat16 *xh, *xl, *uh, *ul, *dh, *yh, *yl;
    __nv_bfloat16 *wih, *wil, *dsh, *woh, *wol, *xph, *xpl;
    cudaGetSymbolAddress((void**)&xr,   g_xr);
    cudaGetSymbolAddress((void**)&dp,   g_dp);
    cudaGetSymbolAddress((void**)&xdbl, g_xdbl);
    cudaGetSymbolAddress((void**)&csum, g_csum);
    cudaGetSymbolAddress((void**)&xh,  g_xh);  cudaGetSymbolAddress((void**)&xl,  g_xl);
    cudaGetSymbolAddress((void**)&uh,  g_uh);  cudaGetSymbolAddress((void**)&ul,  g_ul);
    cudaGetSymbolAddress((void**)&dh,  g_dh);
    cudaGetSymbolAddress((void**)&yh,  g_yh);  cudaGetSymbolAddress((void**)&yl,  g_yl);
    cudaGetSymbolAddress((void**)&wih, g_wih); cudaGetSymbolAddress((void**)&wil, g_wil);
    cudaGetSymbolAddress((void**)&dsh, g_dsh);
    cudaGetSymbolAddress((void**)&woh, g_woh); cudaGetSymbolAddress((void**)&wol, g_wol);
    cudaGetSymbolAddress((void**)&xph, g_xph); cudaGetSymbolAddress((void**)&xpl, g_xpl);

    const int SM3_128 = 2 * (20480 + 2 * 128 * PITCH);   // 81920
    const int SM3_64  = 2 * (20480 + 2 * 64  * PITCH);   // 61440
    cudaFuncSetAttribute((const void*)mma_gemm<0,3,128>, cudaFuncAttributeMaxDynamicSharedMemorySize, SM3_128);
    cudaFuncSetAttribute((const void*)mma_gemm<1,3,128>, cudaFuncAttributeMaxDynamicSharedMemorySize, SM3_128);
    cudaFuncSetAttribute((const void*)mma_gemm<2,3,64>,  cudaFuncAttributeMaxDynamicSharedMemorySize, SM3_64);
    cudaFuncSetAttribute((const void*)mma_gemm<3,1,128>, cudaFuncAttributeMaxDynamicSharedMemorySize, SM3_128);
    cudaFuncSetAttribute((const void*)dtproj_mma,        cudaFuncAttributeMaxDynamicSharedMemorySize, 20480);

    // 0) conversions + colsum (one launch)
    cvt_all<<<18450, 256>>>(x, inw, outw, dis, xpw, dtw);

    // 1) xr = x @ in_proj_w^T   [32768 x 1024]
    mma_gemm<0,3,128><<<dim3(8, SEQ / 128), 256, SM3_128>>>(xh, xl, wih, wil, xr, nullptr, 1024, 512, 1024);

    // 2) u = silu(conv(xs))  (+ bf16 split)
    conv_silu_kernel<<<(SEQ / 4 * 128) / 256, 256>>>(convw, convb);

    // 3) xdbl = u @ x_proj_w^T  (BN=64 tile; fp32 cols<36 + bf16 cols<32)
    mma_gemm<2,3,64><<<dim3(1, SEQ / 128), 256, SM3_64>>>(uh, ul, xph, xpl, xdbl, nullptr, 64, 512, 36);

    // 4) delta residual via tensor cores (K=32)
    dtproj_mma<<<dim3(DM / 128, SEQ / 128), 256, 20480>>>(dtb);

    // 5) delta_p = ln2*colsum(dis) + residual @ dis
    mma_gemm<3,1,128><<<dim3(DM / 128, SEQ / 128), 256, SM3_128>>>(dh, nullptr, dsh, nullptr, dp, csum, DM, 512, DM);

    // 6-8) chunked selective scan
    scanA_kernel<<<NCH, 128>>>(alog);
    scanB_kernel<<<8, 128>>>();
    scanC_kernel<<<NCH, 128>>>(alog, Dw);

    // 9) out = y @ out_proj_w^T, finite filter
    mma_gemm<1,3,128><<<dim3(DM / 128, SEQ / 128), 256, SM3_128>>>(yh, yl, woh, wol, out, nullptr, DM, 512, DM);
}

// round 12
// speedup vs baseline: 2.1850x; 1.2642x over previous
#include <cuda_runtime.h>
#include <cuda_fp16.h>
#include <math.h>
#include <stdint.h>

#define SEQ   32768
#define DM    512
#define NCH   512
#define TCH   64
#define C_LN2 0.69314718055994531f

// ---------------- scratch (device globals) -----------------------------------
__device__ float g_xr  [(size_t)SEQ * 1024];
__device__ float g_u   [(size_t)SEQ * DM];
__device__ float g_xdbl[(size_t)SEQ * 36];
__device__ float g_dp  [(size_t)SEQ * DM];
__device__ float g_P   [NCH * 1024];
__device__ float g_S   [NCH * 1024];
__device__ float g_H   [NCH * 1024];
__device__ float g_csum[DM];

// fp16 operands: activations single, weights split
__device__ __half g_xh [(size_t)SEQ * DM];      // x fp16
__device__ __half g_uh [(size_t)SEQ * DM];      // u fp16
__device__ __half g_dh [(size_t)SEQ * DM];      // delta residual fp16
__device__ __half g_yh [(size_t)SEQ * DM];      // y fp16
__device__ __half g_xbh[(size_t)SEQ * 32];      // xdbl cols 0..31 fp16
__device__ __half g_wih[1024 * 512], g_wil[1024 * 512];   // in_proj_w split
__device__ __half g_dsh[512 * 512];                        // dis^T fp16
__device__ __half g_woh[512 * 512],  g_wol[512 * 512];     // out_proj_w split
__device__ __half g_xph[128 * 512],  g_xpl[128 * 512];     // x_proj_w padded split
__device__ __half g_dtwh[512 * 32];                        // dt_proj_w fp16

// ---------------- PTX helpers ---------------------------------------------------
__device__ __forceinline__ uint32_t smem_u32(const void* p) {
    uint32_t a;
    asm("{ .reg .u64 t; cvta.to.shared.u64 t, %1; cvt.u32.u64 %0, t; }" : "=r"(a) : "l"(p));
    return a;
}
#define CP_ASYNC16(dst, src) \
    asm volatile("cp.async.cg.shared.global [%0], [%1], 16;" :: "r"(dst), "l"(src) : "memory")
#define CP_COMMIT() asm volatile("cp.async.commit_group;" ::: "memory")
#define CP_WAIT1()  asm volatile("cp.async.wait_group 1;" ::: "memory")
#define CP_WAIT0()  asm volatile("cp.async.wait_group 0;" ::: "memory")

__device__ __forceinline__ void ldsm4(uint32_t* r, uint32_t addr) {
    asm volatile("ldmatrix.sync.aligned.m8n8.x4.shared.b16 {%0,%1,%2,%3}, [%4];"
                 : "=r"(r[0]), "=r"(r[1]), "=r"(r[2]), "=r"(r[3]) : "r"(addr));
}
__device__ __forceinline__ void mma16816(float* c, const uint32_t* a,
                                         uint32_t b0, uint32_t b1) {
    asm volatile("mma.sync.aligned.m16n8k16.row.col.f32.f16.f16.f32 "
                 "{%0,%1,%2,%3}, {%4,%5,%6,%7}, {%8,%9}, {%0,%1,%2,%3};"
                 : "+f"(c[0]), "+f"(c[1]), "+f"(c[2]), "+f"(c[3])
                 : "r"(a[0]), "r"(a[1]), "r"(a[2]), "r"(a[3]), "r"(b0), "r"(b1));
}

// ---------------- math helpers --------------------------------------------------
__device__ __forceinline__ float softplusf(float x) {
    float ax = fabsf(x);
    if (ax < 0.25f) {
        float x2 = x * x;
        return C_LN2 + 0.5f * x
             + x2 * (0.125f + x2 * (-1.0f/192.0f + x2 * (1.0f/2880.0f)));
    }
    return fmaxf(x, 0.0f) + log1pf(expf(-ax));
}
__device__ __forceinline__ float siluf(float x) { return x / (1.0f + __expf(-x)); }
__device__ __forceinline__ void split_fp16(float v, __half& h, __half& l) {
    h = __float2half(v);
    l = __float2half(v - __half2float(h));
}

// ---------------- combined conversion kernel -------------------------------------
// seg0 x:16384  seg1 inw(split):512  seg2 outw(split):256  seg3 dis^T:1024
// seg4 xpw(split,padded):256  seg5 dtw:16  seg6 colsum:2
__global__ __launch_bounds__(256)
void cvt_all(const float* __restrict__ x, const float* __restrict__ inw,
             const float* __restrict__ outw, const float* __restrict__ dis,
             const float* __restrict__ xpw, const float* __restrict__ dtw)
{
    int b = blockIdx.x;
    if (b < 16384) {
        int i = b * 256 + threadIdx.x;
        float4 v = reinterpret_cast<const float4*>(x)[i];
        __half h[4] = { __float2half(v.x), __float2half(v.y),
                        __float2half(v.z), __float2half(v.w) };
        reinterpret_cast<uint2*>(g_xh)[i] = *reinterpret_cast<uint2*>(h);
    } else if (b < 16896) {
        int i = (b - 16384) * 256 + threadIdx.x;
        float4 v = reinterpret_cast<const float4*>(inw)[i];
        __half h[4], l[4];
        split_fp16(v.x, h[0], l[0]); split_fp16(v.y, h[1], l[1]);
        split_fp16(v.z, h[2], l[2]); split_fp16(v.w, h[3], l[3]);
        reinterpret_cast<uint2*>(g_wih)[i] = *reinterpret_cast<uint2*>(h);
        reinterpret_cast<uint2*>(g_wil)[i] = *reinterpret_cast<uint2*>(l);
    } else if (b < 17152) {
        int i = (b - 16896) * 256 + threadIdx.x;
        float4 v = reinterpret_cast<const float4*>(outw)[i];
        __half h[4], l[4];
        split_fp16(v.x, h[0], l[0]); split_fp16(v.y, h[1], l[1]);
        split_fp16(v.z, h[2], l[2]); split_fp16(v.w, h[3], l[3]);
        reinterpret_cast<uint2*>(g_woh)[i] = *reinterpret_cast<uint2*>(h);
        reinterpret_cast<uint2*>(g_wol)[i] = *reinterpret_cast<uint2*>(l);
    } else if (b < 18176) {
        int idx = (b - 17152) * 256 + threadIdx.x;
        int n = idx >> 9, k = idx & 511;
        g_dsh[idx] = __float2half(dis[k * 512 + n]);
    } else if (b < 18432) {
        int idx = (b - 18176) * 256 + threadIdx.x;   // 128x512 padded
        int r = idx >> 9;
        __half h = __float2half(0.0f), l = h;
        if (r < 36) split_fp16(xpw[idx], h, l);
        g_xph[idx] = h; g_xpl[idx] = l;
    } else if (b < 18448) {
        int i = (b - 18432) * 256 + threadIdx.x;     // 4096 float4
        float4 v = reinterpret_cast<const float4*>(dtw)[i];
        __half h[4] = { __float2half(v.x), __float2half(v.y),
                        __float2half(v.z), __float2half(v.w) };
        reinterpret_cast<uint2*>(g_dtwh)[i] = *reinterpret_cast<uint2*>(h);
    } else {
        int n = (b - 18448) * 256 + threadIdx.x;
        float s = 0.0f;
        #pragma unroll 8
        for (int k = 0; k < 512; k++) s += dis[k * 512 + n];
        g_csum[n] = s * C_LN2;
    }
}

// ---------------- mma.sync fp16 GEMM ---------------------------------------------
// TERMS=2: C = A @ (Bh+Bl)^T.   TERMS=1: C = A @ Bh^T.
// CTA 128m x BNn, 256 threads (8 warps, 4m x 2n), warp tile 32 x BN/2, BK=32, 2 stages.
// Stage: A(10240) | Bh(BN*PITCH) | [Bl(BN*PITCH) if TERMS==2]
// EPI: 0 plain, 1 finite filter, 2 narrow store (fp32 cols<ldc + fp16 cols<32 -> g_xbh),
//      3 += bias2[col]
#define PITCH   80
template <int EPI, int TERMS, int BN>
__global__ __launch_bounds__(256, 2)
void mma_gemm(const __half* __restrict__ A,
              const __half* __restrict__ Bh, const __half* __restrict__ Bl,
              float* __restrict__ C, const float* __restrict__ bias2,
              int N, int K, int ldc)
{
    constexpr int WN = BN / 2;
    constexpr int TB = WN / 16;
    constexpr uint32_t BREG = BN * PITCH;
    constexpr uint32_t STAGE = 10240 + TERMS * BREG;

    extern __shared__ char dsm[];
    const uint32_t sb = smem_u32(dsm);
    const int tid = threadIdx.x;
    const int wid = tid >> 5, L = tid & 31;
    const int wm = wid >> 1, wn = wid & 1;
    const int m0 = blockIdx.y * 128, n0 = blockIdx.x * BN;

    const __half* srcA = A + (size_t)m0 * K;
    const __half* srcB[2] = { Bh + (size_t)n0 * K,
                              (TERMS == 2 ? Bl : Bh) + (size_t)n0 * K };

    const int lrow = L & 15;
    const int lcolB = (L >> 4) * 16;
    const uint32_t aBase = sb + (wm * 32 + lrow) * PITCH + lcolB;
    const uint32_t bBase = sb + 10240 + (wn * WN + lrow) * PITCH + lcolB;

    float acc[2][2 * TB][4];
    #pragma unroll
    for (int i = 0; i < 2; i++)
        #pragma unroll
        for (int j = 0; j < 2 * TB; j++)
            #pragma unroll
            for (int q = 0; q < 4; q++) acc[i][j][q] = 0.0f;

    const int nk = K / 32;

    auto load_stage = [&](int ks, int buf) {
        uint32_t dst0 = sb + buf * STAGE;
        int k0 = ks * 32;
        constexpr int ITERS = (512 + TERMS * BN * 4) / 256;
        #pragma unroll
        for (int it = 0; it < ITERS; it++) {
            int cid = it * 256 + tid;
            if (cid < 512) {
                int r = cid >> 2, c = cid & 3;
                CP_ASYNC16(dst0 + r * PITCH + c * 16, srcA + (size_t)r * K + k0 + c * 8);
            } else {
                int w2 = cid - 512;
                int matB = w2 / (BN * 4);
                int rw = w2 - matB * BN * 4;
                int r = rw >> 2, c = rw & 3;
                CP_ASYNC16(dst0 + 10240 + matB * BREG + r * PITCH + c * 16,
                           srcB[matB] + (size_t)r * K + k0 + c * 8);
            }
        }
    };

    load_stage(0, 0); CP_COMMIT();
    load_stage(1, 1); CP_COMMIT();

    for (int ks = 0; ks < nk; ks++) {
        CP_WAIT1();
        __syncthreads();
        uint32_t bo = (ks & 1) * STAGE;
        #pragma unroll
        for (int kk = 0; kk < 2; kk++) {
            uint32_t ko = kk * 32;
            uint32_t ah[2][4], b[TB][4];
            #pragma unroll
            for (int mi = 0; mi < 2; mi++)
                ldsm4(ah[mi], aBase + bo + mi * 1280 + ko);
            #pragma unroll
            for (int t = 0; t < TB; t++)
                ldsm4(b[t], bBase + bo + t * 1280 + ko);
            #pragma unroll
            for (int mi = 0; mi < 2; mi++)
                #pragma unroll
                for (int t = 0; t < TB; t++) {
                    mma16816(acc[mi][2*t+0], ah[mi], b[t][0], b[t][2]);
                    mma16816(acc[mi][2*t+1], ah[mi], b[t][1], b[t][3]);
                }
            if (TERMS == 2) {
                #pragma unroll
                for (int t = 0; t < TB; t++)
                    ldsm4(b[t], bBase + bo + BREG + t * 1280 + ko);
                #pragma unroll
                for (int mi = 0; mi < 2; mi++)
                    #pragma unroll
                    for (int t = 0; t < TB; t++) {
                        mma16816(acc[mi][2*t+0], ah[mi], b[t][0], b[t][2]);
                        mma16816(acc[mi][2*t+1], ah[mi], b[t][1], b[t][3]);
                    }
            }
        }
        __syncthreads();
        if (ks + 2 < nk) load_stage(ks + 2, ks & 1);
        CP_COMMIT();
    }

    // epilogue
    #pragma unroll
    for (int mi = 0; mi < 2; mi++) {
        #pragma unroll
        for (int j = 0; j < 2 * TB; j++) {
            int row = m0 + wm * 32 + mi * 16 + (L >> 2);
            int col = n0 + wn * WN + j * 8 + (L & 3) * 2;
            float v0 = acc[mi][j][0], v1 = acc[mi][j][1];
            float v2 = acc[mi][j][2], v3 = acc[mi][j][3];
            if (EPI == 1) {
                v0 = isfinite(v0) ? v0 : 0.0f; v1 = isfinite(v1) ? v1 : 0.0f;
                v2 = isfinite(v2) ? v2 : 0.0f; v3 = isfinite(v3) ? v3 : 0.0f;
            }
            if (EPI == 3) {
                float b0 = bias2[col], b1 = bias2[col + 1];
                v0 += b0; v1 += b1; v2 += b0; v3 += b1;
            }
            if (EPI == 2) {
                if (col + 1 < ldc) {
                    *reinterpret_cast<float2*>(C + (size_t)row * ldc + col)       = make_float2(v0, v1);
                    *reinterpret_cast<float2*>(C + (size_t)(row + 8) * ldc + col) = make_float2(v2, v3);
                }
                if (col + 1 < 32) {
                    __half p0[2] = { __float2half(v0), __float2half(v1) };
                    __half p1[2] = { __float2half(v2), __float2half(v3) };
                    *reinterpret_cast<uint32_t*>(g_xbh + (size_t)row * 32 + col)       = *reinterpret_cast<uint32_t*>(p0);
                    *reinterpret_cast<uint32_t*>(g_xbh + (size_t)(row + 8) * 32 + col) = *reinterpret_cast<uint32_t*>(p1);
                }
            } else {
                *reinterpret_cast<float2*>(C + (size_t)row * ldc + col)       = make_float2(v0, v1);
                *reinterpret_cast<float2*>(C + (size_t)(row + 8) * ldc + col) = make_float2(v2, v3);
            }
        }
    }
}

// ---------------- dtproj via tensor cores (K=32, single stage) -------------------
__global__ __launch_bounds__(256)
void dtproj_mma(const float* __restrict__ dtb)
{
    extern __shared__ char dsm[];
    const uint32_t sb = smem_u32(dsm);
    const int tid = threadIdx.x;
    const int wid = tid >> 5, L = tid & 31;
    const int wm = wid >> 1, wn = wid & 1;
    const int m0 = blockIdx.y * 128, n0 = blockIdx.x * 128;

    #pragma unroll
    for (int it = 0; it < 4; it++) {
        int cid = it * 256 + tid;
        int isB = cid >> 9, w = cid & 511;
        int r = w >> 2, c = w & 3;
        uint32_t dst = sb + isB * 10240 + r * PITCH + c * 16;
        const __half* src = isB ? (g_dtwh + (size_t)(n0 + r) * 32 + c * 8)
                                : (g_xbh + (size_t)(m0 + r) * 32 + c * 8);
        CP_ASYNC16(dst, src);
    }
    CP_COMMIT();
    CP_WAIT0();
    __syncthreads();

    const int lrow = L & 15;
    const int lcolB = (L >> 4) * 16;
    const uint32_t aBase = sb + (wm * 32 + lrow) * PITCH + lcolB;
    const uint32_t bBase = sb + 10240 + (wn * 64 + lrow) * PITCH + lcolB;

    float acc[2][8][4];
    #pragma unroll
    for (int i = 0; i < 2; i++)
        #pragma unroll
        for (int j = 0; j < 8; j++)
            #pragma unroll
            for (int q = 0; q < 4; q++) acc[i][j][q] = 0.0f;

    #pragma unroll
    for (int kk = 0; kk < 2; kk++) {
        uint32_t ko = kk * 32;
        uint32_t ah[2][4], b[4][4];
        #pragma unroll
        for (int mi = 0; mi < 2; mi++)
            ldsm4(ah[mi], aBase + mi * 1280 + ko);
        #pragma unroll
        for (int t = 0; t < 4; t++)
            ldsm4(b[t], bBase + t * 1280 + ko);
        #pragma unroll
        for (int mi = 0; mi < 2; mi++)
            #pragma unroll
            for (int t = 0; t < 4; t++) {
                mma16816(acc[mi][2*t+0], ah[mi], b[t][0], b[t][2]);
                mma16816(acc[mi][2*t+1], ah[mi], b[t][1], b[t][3]);
            }
    }

    #pragma unroll
    for (int mi = 0; mi < 2; mi++) {
        #pragma unroll
        for (int j = 0; j < 8; j++) {
            int row = m0 + wm * 32 + mi * 16 + (L >> 2);
            int col = n0 + wn * 64 + j * 8 + (L & 3) * 2;
            float b0 = dtb[col], b1 = dtb[col + 1];
            __half p0[2] = {
                __float2half(softplusf(acc[mi][j][0] + b0) - C_LN2),
                __float2half(softplusf(acc[mi][j][1] + b1) - C_LN2) };
            __half p1[2] = {
                __float2half(softplusf(acc[mi][j][2] + b0) - C_LN2),
                __float2half(softplusf(acc[mi][j][3] + b1) - C_LN2) };
            *reinterpret_cast<uint32_t*>(g_dh + (size_t)row * 512 + col)       = *reinterpret_cast<uint32_t*>(p0);
            *reinterpret_cast<uint32_t*>(g_dh + (size_t)(row + 8) * 512 + col) = *reinterpret_cast<uint32_t*>(p1);
        }
    }
}

// ---------------- depthwise conv + silu: 4 timesteps x 4 channels per thread -----
__global__ __launch_bounds__(256)
void conv_silu_kernel(const float* __restrict__ cw, const float* __restrict__ cb)
{
    int g = blockIdx.x * 256 + threadIdx.x;
    int t0 = (g >> 7) * 4;
    int d4 = (g & 127) * 4;
    const float* base = g_xr + d4;

    float4 row[7];
    #pragma unroll
    for (int k = 0; k < 7; k++) {
        int t = t0 - 3 + k;
        row[k] = (t >= 0) ? *reinterpret_cast<const float4*>(base + (size_t)t * 1024)
                          : make_float4(0.f, 0.f, 0.f, 0.f);
    }
    float4 bv = *reinterpret_cast<const float4*>(cb + d4);
    const float* bb = &bv.x;
    float4 w[4];
    #pragma unroll
    for (int j = 0; j < 4; j++) w[j] = reinterpret_cast<const float4*>(cw)[d4 + j];

    #pragma unroll
    for (int i = 0; i < 4; i++) {
        float u[4];
        #pragma unroll
        for (int j = 0; j < 4; j++) {
            float a = bb[j];
            a = fmaf(w[j].x, (&row[i+0].x)[j], a);
            a = fmaf(w[j].y, (&row[i+1].x)[j], a);
            a = fmaf(w[j].z, (&row[i+2].x)[j], a);
            a = fmaf(w[j].w, (&row[i+3].x)[j], a);
            u[j] = siluf(a);
        }
        size_t o = (size_t)(t0 + i) * 512 + d4;
        *reinterpret_cast<float4*>(g_u + o) = make_float4(u[0], u[1], u[2], u[3]);
        __half h[4] = { __float2half(u[0]), __float2half(u[1]),
                        __float2half(u[2]), __float2half(u[3]) };
        *reinterpret_cast<uint2*>(g_uh + o) = *reinterpret_cast<uint2*>(h);
    }
}

// ---------------- scan passes (TCH=64, thread = 4 channels) ----------------------
__global__ __launch_bounds__(128)
void scanA_kernel(const float* __restrict__ Alog)
{
    int c  = blockIdx.x;
    int d4 = threadIdx.x * 4;
    float A0[4], A1[4], P0[4], P1[4], S0[4], S1[4];
    #pragma unroll
    for (int j = 0; j < 4; j++) {
        A0[j] = -expf(Alog[(d4 + j) * 2 + 0]);
        A1[j] = -expf(Alog[(d4 + j) * 2 + 1]);
        P0[j] = 1.f; P1[j] = 1.f; S0[j] = 0.f; S1[j] = 0.f;
    }
    const float* dp = g_dp + (size_t)c * TCH * DM + d4;
    const float* uu = g_u  + (size_t)c * TCH * DM + d4;
    const float* xd = g_xdbl + (size_t)c * TCH * 36;
    #pragma unroll 4
    for (int i = 0; i < TCH; i++) {
        float4 dpv = *reinterpret_cast<const float4*>(dp + (size_t)i * DM);
        float4 uv  = *reinterpret_cast<const float4*>(uu + (size_t)i * DM);
        float B0 = xd[i * 36 + 32], B1 = xd[i * 36 + 33];
        const float* dj = &dpv.x; const float* uj = &uv.x;
        #pragma unroll
        for (int j = 0; j < 4; j++) {
            float x0 = dj[j] * A0[j], x1 = dj[j] * A1[j];
            float a0 = 0.f, a1 = 0.f;
            if (fmaxf(x0, x1) > -87.0f) { a0 = __expf(x0); a1 = __expf(x1); }
            float bu = dj[j] * uj[j];
            S0[j] = fmaf(a0, S0[j], bu * B0);
            S1[j] = fmaf(a1, S1[j], bu * B1);
            P0[j] *= a0; P1[j] *= a1;
        }
    }
    #pragma unroll
    for (int j = 0; j < 4; j++) {
        int dn = (d4 + j) * 2;
        g_P[c * 1024 + dn] = P0[j]; g_P[c * 1024 + dn + 1] = P1[j];
        g_S[c * 1024 + dn] = S0[j]; g_S[c * 1024 + dn + 1] = S1[j];
    }
}

__global__ __launch_bounds__(128)
void scanB_kernel()
{
    int dn = blockIdx.x * 128 + threadIdx.x;
    float h = 0.0f;
    for (int cb = 0; cb < NCH; cb += 16) {
        float p[16], s[16];
        #pragma unroll
        for (int i = 0; i < 16; i++) {
            p[i] = g_P[(cb + i) * 1024 + dn];
            s[i] = g_S[(cb + i) * 1024 + dn];
        }
        #pragma unroll
        for (int i = 0; i < 16; i++) {
            g_H[(cb + i) * 1024 + dn] = h;
            h = fmaf(p[i], h, s[i]);
        }
    }
}

__global__ __launch_bounds__(128)
void scanC_kernel(const float* __restrict__ Alog, const float* __restrict__ Dw)
{
    int c  = blockIdx.x;
    int d4 = threadIdx.x * 4;
    float A0[4], A1[4], h0[4], h1[4];
    #pragma unroll
    for (int j = 0; j < 4; j++) {
        A0[j] = -expf(Alog[(d4 + j) * 2 + 0]);
        A1[j] = -expf(Alog[(d4 + j) * 2 + 1]);
        h0[j] = g_H[c * 1024 + (d4 + j) * 2];
        h1[j] = g_H[c * 1024 + (d4 + j) * 2 + 1];
    }
    float4 Dv4 = *reinterpret_cast<const float4*>(Dw + d4);
    const float* Dv = &Dv4.x;
    const float* dp = g_dp + (size_t)c * TCH * DM + d4;
    const float* uu = g_u  + (size_t)c * TCH * DM + d4;
    const float* xd = g_xdbl + (size_t)c * TCH * 36;
    const float* rs = g_xr + (size_t)c * TCH * 1024 + 512 + d4;
    __half* yh = g_yh + (size_t)c * TCH * DM + d4;
    #pragma unroll 4
    for (int i = 0; i < TCH; i++) {
        float4 dpv = *reinterpret_cast<const float4*>(dp + (size_t)i * DM);
        float4 uv  = *reinterpret_cast<const float4*>(uu + (size_t)i * DM);
        float4 rv  = *reinterpret_cast<const float4*>(rs + (size_t)i * 1024);
        float B0 = xd[i * 36 + 32], B1 = xd[i * 36 + 33];
        float C0 = xd[i * 36 + 34], C1 = xd[i * 36 + 35];
        const float* dj = &dpv.x; const float* uj = &uv.x; const float* rj = &rv.x;
        __half oh[4];
        #pragma unroll
        for (int j = 0; j < 4; j++) {
            float x0 = dj[j] * A0[j], x1 = dj[j] * A1[j];
            float a0 = 0.f, a1 = 0.f;
            if (fmaxf(x0, x1) > -87.0f) { a0 = __expf(x0); a1 = __expf(x1); }
            float bu = dj[j] * uj[j];
            h0[j] = fmaf(a0, h0[j], bu * B0);
            h1[j] = fmaf(a1, h1[j], bu * B1);
            float y = fmaf(h0[j], C0, fmaf(h1[j], C1, uj[j] * Dv[j]));
            y *= siluf(rj[j]);
            oh[j] = __float2half(y);
        }
        *reinterpret_cast<uint2*>(yh + (size_t)i * DM) = *reinterpret_cast<uint2*>(oh);
    }
}

// ---------------- launch --------------------------------------------------------
extern "C" void kernel_launch(void* const* d_in, const int* in_sizes, int n_in,
                              void* d_out, int out_size)
{
    const float* x     = (const float*)d_in[0];
    const float* dis   = (const float*)d_in[1];
    const float* inw   = (const float*)d_in[2];
    const float* convw = (const float*)d_in[3];
    const float* convb = (const float*)d_in[4];
    const float* xpw   = (const float*)d_in[5];
    const float* dtw   = (const float*)d_in[6];
    const float* dtb   = (const float*)d_in[7];
    const float* alog  = (const float*)d_in[8];
    const float* Dw    = (const float*)d_in[9];
    const float* outw  = (const float*)d_in[10];
    float* out = (float*)d_out;

    float *xr, *dp, *xdbl, *csum;
    __half *xh, *uh, *dh, *yh;
    __half *wih, *wil, *dsh, *woh, *wol, *xph, *xpl;
    cudaGetSymbolAddress((void**)&xr,   g_xr);
    cudaGetSymbolAddress((void**)&dp,   g_dp);
    cudaGetSymbolAddress((void**)&xdbl, g_xdbl);
    cudaGetSymbolAddress((void**)&csum, g_csum);
    cudaGetSymbolAddress((void**)&xh,  g_xh);
    cudaGetSymbolAddress((void**)&uh,  g_uh);
    cudaGetSymbolAddress((void**)&dh,  g_dh);
    cudaGetSymbolAddress((void**)&yh,  g_yh);
    cudaGetSymbolAddress((void**)&wih, g_wih); cudaGetSymbolAddress((void**)&wil, g_wil);
    cudaGetSymbolAddress((void**)&dsh, g_dsh);
    cudaGetSymbolAddress((void**)&woh, g_woh); cudaGetSymbolAddress((void**)&wol, g_wol);
    cudaGetSymbolAddress((void**)&xph, g_xph); cudaGetSymbolAddress((void**)&xpl, g_xpl);

    const int SM2_128 = 2 * (10240 + 2 * 128 * PITCH);   // 61440
    const int SM2_64  = 2 * (10240 + 2 * 64  * PITCH);   // 40960
    const int SM1_128 = 2 * (10240 + 1 * 128 * PITCH);   // 40960
    cudaFuncSetAttribute((const void*)mma_gemm<0,2,128>, cudaFuncAttributeMaxDynamicSharedMemorySize, SM2_128);
    cudaFuncSetAttribute((const void*)mma_gemm<1,2,128>, cudaFuncAttributeMaxDynamicSharedMemorySize, SM2_128);
    cudaFuncSetAttribute((const void*)mma_gemm<2,2,64>,  cudaFuncAttributeMaxDynamicSharedMemorySize, SM2_64);
    cudaFuncSetAttribute((const void*)mma_gemm<3,1,128>, cudaFuncAttributeMaxDynamicSharedMemorySize, SM1_128);
    cudaFuncSetAttribute((const void*)dtproj_mma,        cudaFuncAttributeMaxDynamicSharedMemorySize, 20480);

    // 0) conversions + colsum
    cvt_all<<<18450, 256>>>(x, inw, outw, dis, xpw, dtw);

    // 1) xr = x @ in_proj_w^T   [32768 x 1024]
    mma_gemm<0,2,128><<<dim3(8, SEQ / 128), 256, SM2_128>>>(xh, wih, wil, xr, nullptr, 1024, 512, 1024);

    // 2) u = silu(conv(xs)) (+ fp16 copy)
    conv_silu_kernel<<<(SEQ / 4 * 128) / 256, 256>>>(convw, convb);

    // 3) xdbl = u @ x_proj_w^T  (BN=64; fp32 cols<36 + fp16 cols<32)
    mma_gemm<2,2,64><<<dim3(1, SEQ / 128), 256, SM2_64>>>(uh, xph, xpl, xdbl, nullptr, 64, 512, 36);

    // 4) delta residual via tensor cores (K=32)
    dtproj_mma<<<dim3(DM / 128, SEQ / 128), 256, 20480>>>(dtb);

    // 5) delta_p = ln2*colsum(dis) + residual @ dis  (1-term fp16)
    mma_gemm<3,1,128><<<dim3(DM / 128, SEQ / 128), 256, SM1_128>>>(dh, dsh, nullptr, dp, csum, DM, 512, DM);

    // 6-8) chunked selective scan
    scanA_kernel<<<NCH, 128>>>(alog);
    scanB_kernel<<<8, 128>>>();
    scanC_kernel<<<NCH, 128>>>(alog, Dw);

    // 9) out = y @ out_proj_w^T, finite filter
    mma_gemm<1,2,128><<<dim3(DM / 128, SEQ / 128), 256, SM2_128>>>(yh, woh, wol, out, nullptr, DM, 512, DM);
}

// round 13
// speedup vs baseline: 2.2546x; 1.0319x over previous
#include <cuda_runtime.h>
#include <cuda_fp16.h>
#include <math.h>
#include <stdint.h>

#define SEQ   32768
#define DM    512
#define NCH   512
#define TCH   64
#define C_LN2 0.69314718055994531f

// ---------------- scratch (device globals) -----------------------------------
__device__ float g_xs  [(size_t)SEQ * DM];      // in_proj cols 0..511 (conv input)
__device__ float g_xdbl[(size_t)SEQ * 36];
__device__ float g_dp  [(size_t)SEQ * DM];
__device__ float g_P   [NCH * 1024];
__device__ float g_S   [NCH * 1024];
__device__ float g_H   [NCH * 1024];
__device__ float g_csum[DM];

__device__ __half g_rsh[(size_t)SEQ * DM];      // silu(res) fp16
__device__ __half g_xh [(size_t)SEQ * DM];      // x fp16
__device__ __half g_uh [(size_t)SEQ * DM];      // u fp16
__device__ __half g_dh [(size_t)SEQ * DM];      // delta residual fp16
__device__ __half g_yh [(size_t)SEQ * DM];      // y fp16
__device__ __half g_xbh[(size_t)SEQ * 32];      // xdbl cols 0..31 fp16
__device__ __half g_wih[1024 * 512], g_wil[1024 * 512];
__device__ __half g_dsh[512 * 512];
__device__ __half g_woh[512 * 512],  g_wol[512 * 512];
__device__ __half g_xph[128 * 512],  g_xpl[128 * 512];
__device__ __half g_dtwh[512 * 32];

// ---------------- PTX helpers ---------------------------------------------------
__device__ __forceinline__ uint32_t smem_u32(const void* p) {
    uint32_t a;
    asm("{ .reg .u64 t; cvta.to.shared.u64 t, %1; cvt.u32.u64 %0, t; }" : "=r"(a) : "l"(p));
    return a;
}
#define CP_ASYNC16(dst, src) \
    asm volatile("cp.async.cg.shared.global [%0], [%1], 16;" :: "r"(dst), "l"(src) : "memory")
#define CP_COMMIT() asm volatile("cp.async.commit_group;" ::: "memory")
#define CP_WAIT1()  asm volatile("cp.async.wait_group 1;" ::: "memory")
#define CP_WAIT0()  asm volatile("cp.async.wait_group 0;" ::: "memory")

__device__ __forceinline__ void ldsm4(uint32_t* r, uint32_t addr) {
    asm volatile("ldmatrix.sync.aligned.m8n8.x4.shared.b16 {%0,%1,%2,%3}, [%4];"
                 : "=r"(r[0]), "=r"(r[1]), "=r"(r[2]), "=r"(r[3]) : "r"(addr));
}
__device__ __forceinline__ void mma16816(float* c, const uint32_t* a,
                                         uint32_t b0, uint32_t b1) {
    asm volatile("mma.sync.aligned.m16n8k16.row.col.f32.f16.f16.f32 "
                 "{%0,%1,%2,%3}, {%4,%5,%6,%7}, {%8,%9}, {%0,%1,%2,%3};"
                 : "+f"(c[0]), "+f"(c[1]), "+f"(c[2]), "+f"(c[3])
                 : "r"(a[0]), "r"(a[1]), "r"(a[2]), "r"(a[3]), "r"(b0), "r"(b1));
}

// ---------------- math helpers --------------------------------------------------
__device__ __forceinline__ float softplusf(float x) {
    float ax = fabsf(x);
    if (ax < 0.25f) {
        float x2 = x * x;
        return C_LN2 + 0.5f * x
             + x2 * (0.125f + x2 * (-1.0f/192.0f + x2 * (1.0f/2880.0f)));
    }
    return fmaxf(x, 0.0f) + log1pf(expf(-ax));
}
__device__ __forceinline__ float siluf(float x) { return x / (1.0f + __expf(-x)); }
__device__ __forceinline__ void split_fp16(float v, __half& h, __half& l) {
    h = __float2half(v);
    l = __float2half(v - __half2float(h));
}

// ---------------- combined conversion kernel -------------------------------------
__global__ __launch_bounds__(256)
void cvt_all(const float* __restrict__ x, const float* __restrict__ inw,
             const float* __restrict__ outw, const float* __restrict__ dis,
             const float* __restrict__ xpw, const float* __restrict__ dtw)
{
    int b = blockIdx.x;
    if (b < 16384) {
        int i = b * 256 + threadIdx.x;
        float4 v = reinterpret_cast<const float4*>(x)[i];
        __half h[4] = { __float2half(v.x), __float2half(v.y),
                        __float2half(v.z), __float2half(v.w) };
        reinterpret_cast<uint2*>(g_xh)[i] = *reinterpret_cast<uint2*>(h);
    } else if (b < 16896) {
        int i = (b - 16384) * 256 + threadIdx.x;
        float4 v = reinterpret_cast<const float4*>(inw)[i];
        __half h[4], l[4];
        split_fp16(v.x, h[0], l[0]); split_fp16(v.y, h[1], l[1]);
        split_fp16(v.z, h[2], l[2]); split_fp16(v.w, h[3], l[3]);
        reinterpret_cast<uint2*>(g_wih)[i] = *reinterpret_cast<uint2*>(h);
        reinterpret_cast<uint2*>(g_wil)[i] = *reinterpret_cast<uint2*>(l);
    } else if (b < 17152) {
        int i = (b - 16896) * 256 + threadIdx.x;
        float4 v = reinterpret_cast<const float4*>(outw)[i];
        __half h[4], l[4];
        split_fp16(v.x, h[0], l[0]); split_fp16(v.y, h[1], l[1]);
        split_fp16(v.z, h[2], l[2]); split_fp16(v.w, h[3], l[3]);
        reinterpret_cast<uint2*>(g_woh)[i] = *reinterpret_cast<uint2*>(h);
        reinterpret_cast<uint2*>(g_wol)[i] = *reinterpret_cast<uint2*>(l);
    } else if (b < 18176) {
        int idx = (b - 17152) * 256 + threadIdx.x;
        int n = idx >> 9, k = idx & 511;
        g_dsh[idx] = __float2half(dis[k * 512 + n]);
    } else if (b < 18432) {
        int idx = (b - 18176) * 256 + threadIdx.x;
        int r = idx >> 9;
        __half h = __float2half(0.0f), l = h;
        if (r < 36) split_fp16(xpw[idx], h, l);
        g_xph[idx] = h; g_xpl[idx] = l;
    } else if (b < 18448) {
        int i = (b - 18432) * 256 + threadIdx.x;
        float4 v = reinterpret_cast<const float4*>(dtw)[i];
        __half h[4] = { __float2half(v.x), __float2half(v.y),
                        __float2half(v.z), __float2half(v.w) };
        reinterpret_cast<uint2*>(g_dtwh)[i] = *reinterpret_cast<uint2*>(h);
    } else {
        int n = (b - 18448) * 256 + threadIdx.x;
        float s = 0.0f;
        #pragma unroll 8
        for (int k = 0; k < 512; k++) s += dis[k * 512 + n];
        g_csum[n] = s * C_LN2;
    }
}

// ---------------- mma.sync fp16 GEMM ---------------------------------------------
// TERMS=2: C = A @ (Bh+Bl)^T.   TERMS=1: C = A @ Bh^T.
// CTA 128m x BNn, 256 threads (8 warps, 4m x 2n), warp tile 32 x BN/2, BK=32, 2 stages.
// EPI: 0 plain, 1 finite filter, 2 narrow (fp32 cols<ldc + fp16 cols<32 -> g_xbh),
//      3 += bias2[col], 4 in_proj split (cols<512 fp32 g_xs; cols>=512 silu fp16 g_rsh)
#define PITCH   80
template <int EPI, int TERMS, int BN>
__global__ __launch_bounds__(256, 2)
void mma_gemm(const __half* __restrict__ A,
              const __half* __restrict__ Bh, const __half* __restrict__ Bl,
              float* __restrict__ C, const float* __restrict__ bias2,
              int N, int K, int ldc)
{
    constexpr int WN = BN / 2;
    constexpr int TB = WN / 16;
    constexpr uint32_t BREG = BN * PITCH;
    constexpr uint32_t STAGE = 10240 + TERMS * BREG;

    extern __shared__ char dsm[];
    const uint32_t sb = smem_u32(dsm);
    const int tid = threadIdx.x;
    const int wid = tid >> 5, L = tid & 31;
    const int wm = wid >> 1, wn = wid & 1;
    const int m0 = blockIdx.y * 128, n0 = blockIdx.x * BN;

    const __half* srcA = A + (size_t)m0 * K;
    const __half* srcB[2] = { Bh + (size_t)n0 * K,
                              (TERMS == 2 ? Bl : Bh) + (size_t)n0 * K };

    const int lrow = L & 15;
    const int lcolB = (L >> 4) * 16;
    const uint32_t aBase = sb + (wm * 32 + lrow) * PITCH + lcolB;
    const uint32_t bBase = sb + 10240 + (wn * WN + lrow) * PITCH + lcolB;

    float acc[2][2 * TB][4];
    #pragma unroll
    for (int i = 0; i < 2; i++)
        #pragma unroll
        for (int j = 0; j < 2 * TB; j++)
            #pragma unroll
            for (int q = 0; q < 4; q++) acc[i][j][q] = 0.0f;

    const int nk = K / 32;

    auto load_stage = [&](int ks, int buf) {
        uint32_t dst0 = sb + buf * STAGE;
        int k0 = ks * 32;
        constexpr int ITERS = (512 + TERMS * BN * 4) / 256;
        #pragma unroll
        for (int it = 0; it < ITERS; it++) {
            int cid = it * 256 + tid;
            if (cid < 512) {
                int r = cid >> 2, c = cid & 3;
                CP_ASYNC16(dst0 + r * PITCH + c * 16, srcA + (size_t)r * K + k0 + c * 8);
            } else {
                int w2 = cid - 512;
                int matB = w2 / (BN * 4);
                int rw = w2 - matB * BN * 4;
                int r = rw >> 2, c = rw & 3;
                CP_ASYNC16(dst0 + 10240 + matB * BREG + r * PITCH + c * 16,
                           srcB[matB] + (size_t)r * K + k0 + c * 8);
            }
        }
    };

    load_stage(0, 0); CP_COMMIT();
    load_stage(1, 1); CP_COMMIT();

    for (int ks = 0; ks < nk; ks++) {
        CP_WAIT1();
        __syncthreads();
        uint32_t bo = (ks & 1) * STAGE;
        #pragma unroll
        for (int kk = 0; kk < 2; kk++) {
            uint32_t ko = kk * 32;
            uint32_t ah[2][4], b[TB][4];
            #pragma unroll
            for (int mi = 0; mi < 2; mi++)
                ldsm4(ah[mi], aBase + bo + mi * 1280 + ko);
            #pragma unroll
            for (int t = 0; t < TB; t++)
                ldsm4(b[t], bBase + bo + t * 1280 + ko);
            #pragma unroll
            for (int mi = 0; mi < 2; mi++)
                #pragma unroll
                for (int t = 0; t < TB; t++) {
                    mma16816(acc[mi][2*t+0], ah[mi], b[t][0], b[t][2]);
                    mma16816(acc[mi][2*t+1], ah[mi], b[t][1], b[t][3]);
                }
            if (TERMS == 2) {
                #pragma unroll
                for (int t = 0; t < TB; t++)
                    ldsm4(b[t], bBase + bo + BREG + t * 1280 + ko);
                #pragma unroll
                for (int mi = 0; mi < 2; mi++)
                    #pragma unroll
                    for (int t = 0; t < TB; t++) {
                        mma16816(acc[mi][2*t+0], ah[mi], b[t][0], b[t][2]);
                        mma16816(acc[mi][2*t+1], ah[mi], b[t][1], b[t][3]);
                    }
            }
        }
        __syncthreads();
        if (ks + 2 < nk) load_stage(ks + 2, ks & 1);
        CP_COMMIT();
    }

    // epilogue
    #pragma unroll
    for (int mi = 0; mi < 2; mi++) {
        #pragma unroll
        for (int j = 0; j < 2 * TB; j++) {
            int row = m0 + wm * 32 + mi * 16 + (L >> 2);
            int col = n0 + wn * WN + j * 8 + (L & 3) * 2;
            float v0 = acc[mi][j][0], v1 = acc[mi][j][1];
            float v2 = acc[mi][j][2], v3 = acc[mi][j][3];
            if (EPI == 1) {
                v0 = isfinite(v0) ? v0 : 0.0f; v1 = isfinite(v1) ? v1 : 0.0f;
                v2 = isfinite(v2) ? v2 : 0.0f; v3 = isfinite(v3) ? v3 : 0.0f;
            }
            if (EPI == 3) {
                float b0 = bias2[col], b1 = bias2[col + 1];
                v0 += b0; v1 += b1; v2 += b0; v3 += b1;
            }
            if (EPI == 4) {
                if (col < 512) {
                    *reinterpret_cast<float2*>(g_xs + (size_t)row * 512 + col)       = make_float2(v0, v1);
                    *reinterpret_cast<float2*>(g_xs + (size_t)(row + 8) * 512 + col) = make_float2(v2, v3);
                } else {
                    int rc = col - 512;
                    __half p0[2] = { __float2half(siluf(v0)), __float2half(siluf(v1)) };
                    __half p1[2] = { __float2half(siluf(v2)), __float2half(siluf(v3)) };
                    *reinterpret_cast<uint32_t*>(g_rsh + (size_t)row * 512 + rc)       = *reinterpret_cast<uint32_t*>(p0);
                    *reinterpret_cast<uint32_t*>(g_rsh + (size_t)(row + 8) * 512 + rc) = *reinterpret_cast<uint32_t*>(p1);
                }
            } else if (EPI == 2) {
                if (col + 1 < ldc) {
                    *reinterpret_cast<float2*>(C + (size_t)row * ldc + col)       = make_float2(v0, v1);
                    *reinterpret_cast<float2*>(C + (size_t)(row + 8) * ldc + col) = make_float2(v2, v3);
                }
                if (col + 1 < 32) {
                    __half p0[2] = { __float2half(v0), __float2half(v1) };
                    __half p1[2] = { __float2half(v2), __float2half(v3) };
                    *reinterpret_cast<uint32_t*>(g_xbh + (size_t)row * 32 + col)       = *reinterpret_cast<uint32_t*>(p0);
                    *reinterpret_cast<uint32_t*>(g_xbh + (size_t)(row + 8) * 32 + col) = *reinterpret_cast<uint32_t*>(p1);
                }
            } else {
                *reinterpret_cast<float2*>(C + (size_t)row * ldc + col)       = make_float2(v0, v1);
                *reinterpret_cast<float2*>(C + (size_t)(row + 8) * ldc + col) = make_float2(v2, v3);
            }
        }
    }
}

// ---------------- dtproj via tensor cores (K=32, single stage) -------------------
__global__ __launch_bounds__(256)
void dtproj_mma(const float* __restrict__ dtb)
{
    extern __shared__ char dsm[];
    const uint32_t sb = smem_u32(dsm);
    const int tid = threadIdx.x;
    const int wid = tid >> 5, L = tid & 31;
    const int wm = wid >> 1, wn = wid & 1;
    const int m0 = blockIdx.y * 128, n0 = blockIdx.x * 128;

    #pragma unroll
    for (int it = 0; it < 4; it++) {
        int cid = it * 256 + tid;
        int isB = cid >> 9, w = cid & 511;
        int r = w >> 2, c = w & 3;
        uint32_t dst = sb + isB * 10240 + r * PITCH + c * 16;
        const __half* src = isB ? (g_dtwh + (size_t)(n0 + r) * 32 + c * 8)
                                : (g_xbh + (size_t)(m0 + r) * 32 + c * 8);
        CP_ASYNC16(dst, src);
    }
    CP_COMMIT();
    CP_WAIT0();
    __syncthreads();

    const int lrow = L & 15;
    const int lcolB = (L >> 4) * 16;
    const uint32_t aBase = sb + (wm * 32 + lrow) * PITCH + lcolB;
    const uint32_t bBase = sb + 10240 + (wn * 64 + lrow) * PITCH + lcolB;

    float acc[2][8][4];
    #pragma unroll
    for (int i = 0; i < 2; i++)
        #pragma unroll
        for (int j = 0; j < 8; j++)
            #pragma unroll
            for (int q = 0; q < 4; q++) acc[i][j][q] = 0.0f;

    #pragma unroll
    for (int kk = 0; kk < 2; kk++) {
        uint32_t ko = kk * 32;
        uint32_t ah[2][4], b[4][4];
        #pragma unroll
        for (int mi = 0; mi < 2; mi++)
            ldsm4(ah[mi], aBase + mi * 1280 + ko);
        #pragma unroll
        for (int t = 0; t < 4; t++)
            ldsm4(b[t], bBase + t * 1280 + ko);
        #pragma unroll
        for (int mi = 0; mi < 2; mi++)
            #pragma unroll
            for (int t = 0; t < 4; t++) {
                mma16816(acc[mi][2*t+0], ah[mi], b[t][0], b[t][2]);
                mma16816(acc[mi][2*t+1], ah[mi], b[t][1], b[t][3]);
            }
    }

    #pragma unroll
    for (int mi = 0; mi < 2; mi++) {
        #pragma unroll
        for (int j = 0; j < 8; j++) {
            int row = m0 + wm * 32 + mi * 16 + (L >> 2);
            int col = n0 + wn * 64 + j * 8 + (L & 3) * 2;
            float b0 = dtb[col], b1 = dtb[col + 1];
            __half p0[2] = {
                __float2half(softplusf(acc[mi][j][0] + b0) - C_LN2),
                __float2half(softplusf(acc[mi][j][1] + b1) - C_LN2) };
            __half p1[2] = {
                __float2half(softplusf(acc[mi][j][2] + b0) - C_LN2),
                __float2half(softplusf(acc[mi][j][3] + b1) - C_LN2) };
            *reinterpret_cast<uint32_t*>(g_dh + (size_t)row * 512 + col)       = *reinterpret_cast<uint32_t*>(p0);
            *reinterpret_cast<uint32_t*>(g_dh + (size_t)(row + 8) * 512 + col) = *reinterpret_cast<uint32_t*>(p1);
        }
    }
}

// ---------------- depthwise conv + silu: 4 timesteps x 4 channels -> fp16 --------
__global__ __launch_bounds__(256)
void conv_silu_kernel(const float* __restrict__ cw, const float* __restrict__ cb)
{
    int g = blockIdx.x * 256 + threadIdx.x;
    int t0 = (g >> 7) * 4;
    int d4 = (g & 127) * 4;
    const float* base = g_xs + d4;

    float4 row[7];
    #pragma unroll
    for (int k = 0; k < 7; k++) {
        int t = t0 - 3 + k;
        row[k] = (t >= 0) ? *reinterpret_cast<const float4*>(base + (size_t)t * 512)
                          : make_float4(0.f, 0.f, 0.f, 0.f);
    }
    float4 bv = *reinterpret_cast<const float4*>(cb + d4);
    const float* bb = &bv.x;
    float4 w[4];
    #pragma unroll
    for (int j = 0; j < 4; j++) w[j] = reinterpret_cast<const float4*>(cw)[d4 + j];

    #pragma unroll
    for (int i = 0; i < 4; i++) {
        __half h[4];
        #pragma unroll
        for (int j = 0; j < 4; j++) {
            float a = bb[j];
            a = fmaf(w[j].x, (&row[i+0].x)[j], a);
            a = fmaf(w[j].y, (&row[i+1].x)[j], a);
            a = fmaf(w[j].z, (&row[i+2].x)[j], a);
            a = fmaf(w[j].w, (&row[i+3].x)[j], a);
            h[j] = __float2half(siluf(a));
        }
        *reinterpret_cast<uint2*>(g_uh + (size_t)(t0 + i) * 512 + d4) = *reinterpret_cast<uint2*>(h);
    }
}

// ---------------- scan passes (TCH=64, thread = 4 channels, fp16 u) --------------
__device__ __forceinline__ void load_h4(const __half* p, float* f) {
    uint2 v = *reinterpret_cast<const uint2*>(p);
    __half2 a = *reinterpret_cast<__half2*>(&v.x);
    __half2 b = *reinterpret_cast<__half2*>(&v.y);
    float2 fa = __half22float2(a), fb = __half22float2(b);
    f[0] = fa.x; f[1] = fa.y; f[2] = fb.x; f[3] = fb.y;
}

__global__ __launch_bounds__(128)
void scanA_kernel(const float* __restrict__ Alog)
{
    int c  = blockIdx.x;
    int d4 = threadIdx.x * 4;
    float A0[4], A1[4], P0[4], P1[4], S0[4], S1[4];
    #pragma unroll
    for (int j = 0; j < 4; j++) {
        A0[j] = -expf(Alog[(d4 + j) * 2 + 0]);
        A1[j] = -expf(Alog[(d4 + j) * 2 + 1]);
        P0[j] = 1.f; P1[j] = 1.f; S0[j] = 0.f; S1[j] = 0.f;
    }
    const float*  dp = g_dp + (size_t)c * TCH * DM + d4;
    const __half* uu = g_uh + (size_t)c * TCH * DM + d4;
    const float*  xd = g_xdbl + (size_t)c * TCH * 36;
    #pragma unroll 4
    for (int i = 0; i < TCH; i++) {
        float4 dpv = *reinterpret_cast<const float4*>(dp + (size_t)i * DM);
        float uj[4];
        load_h4(uu + (size_t)i * DM, uj);
        float B0 = xd[i * 36 + 32], B1 = xd[i * 36 + 33];
        const float* dj = &dpv.x;
        #pragma unroll
        for (int j = 0; j < 4; j++) {
            float x0 = dj[j] * A0[j], x1 = dj[j] * A1[j];
            float a0 = 0.f, a1 = 0.f;
            if (fmaxf(x0, x1) > -87.0f) { a0 = __expf(x0); a1 = __expf(x1); }
            float bu = dj[j] * uj[j];
            S0[j] = fmaf(a0, S0[j], bu * B0);
            S1[j] = fmaf(a1, S1[j], bu * B1);
            P0[j] *= a0; P1[j] *= a1;
        }
    }
    #pragma unroll
    for (int j = 0; j < 4; j++) {
        int dn = (d4 + j) * 2;
        g_P[c * 1024 + dn] = P0[j]; g_P[c * 1024 + dn + 1] = P1[j];
        g_S[c * 1024 + dn] = S0[j]; g_S[c * 1024 + dn + 1] = S1[j];
    }
}

__global__ __launch_bounds__(128)
void scanB_kernel()
{
    int dn = blockIdx.x * 128 + threadIdx.x;
    float h = 0.0f;
    for (int cb = 0; cb < NCH; cb += 16) {
        float p[16], s[16];
        #pragma unroll
        for (int i = 0; i < 16; i++) {
            p[i] = g_P[(cb + i) * 1024 + dn];
            s[i] = g_S[(cb + i) * 1024 + dn];
        }
        #pragma unroll
        for (int i = 0; i < 16; i++) {
            g_H[(cb + i) * 1024 + dn] = h;
            h = fmaf(p[i], h, s[i]);
        }
    }
}

__global__ __launch_bounds__(128)
void scanC_kernel(const float* __restrict__ Alog, const float* __restrict__ Dw)
{
    int c  = blockIdx.x;
    int d4 = threadIdx.x * 4;
    float A0[4], A1[4], h0[4], h1[4];
    #pragma unroll
    for (int j = 0; j < 4; j++) {
        A0[j] = -expf(Alog[(d4 + j) * 2 + 0]);
        A1[j] = -expf(Alog[(d4 + j) * 2 + 1]);
        h0[j] = g_H[c * 1024 + (d4 + j) * 2];
        h1[j] = g_H[c * 1024 + (d4 + j) * 2 + 1];
    }
    float4 Dv4 = *reinterpret_cast<const float4*>(Dw + d4);
    const float* Dv = &Dv4.x;
    const float*  dp = g_dp  + (size_t)c * TCH * DM + d4;
    const __half* uu = g_uh  + (size_t)c * TCH * DM + d4;
    const __half* rs = g_rsh + (size_t)c * TCH * DM + d4;
    const float*  xd = g_xdbl + (size_t)c * TCH * 36;
    __half* yh = g_yh + (size_t)c * TCH * DM + d4;
    #pragma unroll 4
    for (int i = 0; i < TCH; i++) {
        float4 dpv = *reinterpret_cast<const float4*>(dp + (size_t)i * DM);
        float uj[4], rj[4];
        load_h4(uu + (size_t)i * DM, uj);
        load_h4(rs + (size_t)i * DM, rj);
        float B0 = xd[i * 36 + 32], B1 = xd[i * 36 + 33];
        float C0 = xd[i * 36 + 34], C1 = xd[i * 36 + 35];
        const float* dj = &dpv.x;
        __half oh[4];
        #pragma unroll
        for (int j = 0; j < 4; j++) {
            float x0 = dj[j] * A0[j], x1 = dj[j] * A1[j];
            float a0 = 0.f, a1 = 0.f;
            if (fmaxf(x0, x1) > -87.0f) { a0 = __expf(x0); a1 = __expf(x1); }
            float bu = dj[j] * uj[j];
            h0[j] = fmaf(a0, h0[j], bu * B0);
            h1[j] = fmaf(a1, h1[j], bu * B1);
            float y = fmaf(h0[j], C0, fmaf(h1[j], C1, uj[j] * Dv[j]));
            oh[j] = __float2half(y * rj[j]);
        }
        *reinterpret_cast<uint2*>(yh + (size_t)i * DM) = *reinterpret_cast<uint2*>(oh);
    }
}

// ---------------- launch --------------------------------------------------------
extern "C" void kernel_launch(void* const* d_in, const int* in_sizes, int n_in,
                              void* d_out, int out_size)
{
    const float* x     = (const float*)d_in[0];
    const float* dis   = (const float*)d_in[1];
    const float* inw   = (const float*)d_in[2];
    const float* convw = (const float*)d_in[3];
    const float* convb = (const float*)d_in[4];
    const float* xpw   = (const float*)d_in[5];
    const float* dtw   = (const float*)d_in[6];
    const float* dtb   = (const float*)d_in[7];
    const float* alog  = (const float*)d_in[8];
    const float* Dw    = (const float*)d_in[9];
    const float* outw  = (const float*)d_in[10];
    float* out = (float*)d_out;

    float *dp, *xdbl, *csum, *xs;
    __half *xh, *uh, *dh, *yh;
    __half *wih, *wil, *dsh, *woh, *wol, *xph, *xpl;
    cudaGetSymbolAddress((void**)&xs,   g_xs);
    cudaGetSymbolAddress((void**)&dp,   g_dp);
    cudaGetSymbolAddress((void**)&xdbl, g_xdbl);
    cudaGetSymbolAddress((void**)&csum, g_csum);
    cudaGetSymbolAddress((void**)&xh,  g_xh);
    cudaGetSymbolAddress((void**)&uh,  g_uh);
    cudaGetSymbolAddress((void**)&dh,  g_dh);
    cudaGetSymbolAddress((void**)&yh,  g_yh);
    cudaGetSymbolAddress((void**)&wih, g_wih); cudaGetSymbolAddress((void**)&wil, g_wil);
    cudaGetSymbolAddress((void**)&dsh, g_dsh);
    cudaGetSymbolAddress((void**)&woh, g_woh); cudaGetSymbolAddress((void**)&wol, g_wol);
    cudaGetSymbolAddress((void**)&xph, g_xph); cudaGetSymbolAddress((void**)&xpl, g_xpl);

    const int SM2_128 = 2 * (10240 + 2 * 128 * PITCH);   // 61440
    const int SM2_64  = 2 * (10240 + 2 * 64  * PITCH);   // 40960
    const int SM1_128 = 2 * (10240 + 1 * 128 * PITCH);   // 40960
    cudaFuncSetAttribute((const void*)mma_gemm<4,2,128>, cudaFuncAttributeMaxDynamicSharedMemorySize, SM2_128);
    cudaFuncSetAttribute((const void*)mma_gemm<1,2,128>, cudaFuncAttributeMaxDynamicSharedMemorySize, SM2_128);
    cudaFuncSetAttribute((const void*)mma_gemm<2,2,64>,  cudaFuncAttributeMaxDynamicSharedMemorySize, SM2_64);
    cudaFuncSetAttribute((const void*)mma_gemm<3,1,128>, cudaFuncAttributeMaxDynamicSharedMemorySize, SM1_128);
    cudaFuncSetAttribute((const void*)dtproj_mma,        cudaFuncAttributeMaxDynamicSharedMemorySize, 20480);

    // 0) conversions + colsum
    cvt_all<<<18450, 256>>>(x, inw, outw, dis, xpw, dtw);

    // 1) in_proj: cols<512 -> g_xs fp32, cols>=512 -> silu fp16 g_rsh
    mma_gemm<4,2,128><<<dim3(8, SEQ / 128), 256, SM2_128>>>(xh, wih, wil, nullptr, nullptr, 1024, 512, 1024);

    // 2) u = silu(conv(xs)) -> fp16
    conv_silu_kernel<<<(SEQ / 4 * 128) / 256, 256>>>(convw, convb);

    // 3) xdbl = u @ x_proj_w^T
    mma_gemm<2,2,64><<<dim3(1, SEQ / 128), 256, SM2_64>>>(uh, xph, xpl, xdbl, nullptr, 64, 512, 36);

    // 4) delta residual via tensor cores
    dtproj_mma<<<dim3(DM / 128, SEQ / 128), 256, 20480>>>(dtb);

    // 5) delta_p = ln2*colsum(dis) + residual @ dis
    mma_gemm<3,1,128><<<dim3(DM / 128, SEQ / 128), 256, SM1_128>>>(dh, dsh, nullptr, dp, csum, DM, 512, DM);

    // 6-8) chunked selective scan
    scanA_kernel<<<NCH, 128>>>(alog);
    scanB_kernel<<<8, 128>>>();
    scanC_kernel<<<NCH, 128>>>(alog, Dw);

    // 9) out = y @ out_proj_w^T, finite filter
    mma_gemm<1,2,128><<<dim3(DM / 128, SEQ / 128), 256, SM2_128>>>(yh, woh, wol, out, nullptr, DM, 512, DM);
}

// round 14
// speedup vs baseline: 2.2773x; 1.0101x over previous
#include <cuda_runtime.h>
#include <cuda_fp16.h>
#include <math.h>
#include <stdint.h>

#define SEQ   32768
#define DM    512
#define NCH   512
#define TCH   64
#define C_LN2 0.69314718055994531f

// ---------------- scratch (device globals) -----------------------------------
__device__ float g_xdbl[(size_t)SEQ * 36];
__device__ float g_P   [NCH * 1024];
__device__ float g_S   [NCH * 1024];
__device__ float g_H   [NCH * 1024];
__device__ float g_csum[DM];

__device__ __half g_xsh[(size_t)SEQ * DM];      // in_proj cols 0..511 fp16 (conv input)
__device__ __half g_rsh[(size_t)SEQ * DM];      // silu(res) fp16
__device__ __half g_dph[(size_t)SEQ * DM];      // delta_p residual fp16 (dp = csum + this)
__device__ __half g_xh [(size_t)SEQ * DM];      // x fp16
__device__ __half g_uh [(size_t)SEQ * DM];      // u fp16
__device__ __half g_dh [(size_t)SEQ * DM];      // delta residual fp16
__device__ __half g_yh [(size_t)SEQ * DM];      // y fp16
__device__ __half g_xbh[(size_t)SEQ * 32];      // xdbl cols 0..31 fp16
__device__ __half g_wih[1024 * 512], g_wil[1024 * 512];
__device__ __half g_dsh[512 * 512];
__device__ __half g_woh[512 * 512],  g_wol[512 * 512];
__device__ __half g_xph[128 * 512],  g_xpl[128 * 512];
__device__ __half g_dtwh[512 * 32];

// ---------------- PTX helpers ---------------------------------------------------
__device__ __forceinline__ uint32_t smem_u32(const void* p) {
    uint32_t a;
    asm("{ .reg .u64 t; cvta.to.shared.u64 t, %1; cvt.u32.u64 %0, t; }" : "=r"(a) : "l"(p));
    return a;
}
#define CP_ASYNC16(dst, src) \
    asm volatile("cp.async.cg.shared.global [%0], [%1], 16;" :: "r"(dst), "l"(src) : "memory")
#define CP_COMMIT() asm volatile("cp.async.commit_group;" ::: "memory")
#define CP_WAIT1()  asm volatile("cp.async.wait_group 1;" ::: "memory")
#define CP_WAIT0()  asm volatile("cp.async.wait_group 0;" ::: "memory")

__device__ __forceinline__ void ldsm4(uint32_t* r, uint32_t addr) {
    asm volatile("ldmatrix.sync.aligned.m8n8.x4.shared.b16 {%0,%1,%2,%3}, [%4];"
                 : "=r"(r[0]), "=r"(r[1]), "=r"(r[2]), "=r"(r[3]) : "r"(addr));
}
__device__ __forceinline__ void mma16816(float* c, const uint32_t* a,
                                         uint32_t b0, uint32_t b1) {
    asm volatile("mma.sync.aligned.m16n8k16.row.col.f32.f16.f16.f32 "
                 "{%0,%1,%2,%3}, {%4,%5,%6,%7}, {%8,%9}, {%0,%1,%2,%3};"
                 : "+f"(c[0]), "+f"(c[1]), "+f"(c[2]), "+f"(c[3])
                 : "r"(a[0]), "r"(a[1]), "r"(a[2]), "r"(a[3]), "r"(b0), "r"(b1));
}

// ---------------- math helpers --------------------------------------------------
__device__ __forceinline__ float softplusf(float x) {
    float ax = fabsf(x);
    if (ax < 0.25f) {
        float x2 = x * x;
        return C_LN2 + 0.5f * x
             + x2 * (0.125f + x2 * (-1.0f/192.0f + x2 * (1.0f/2880.0f)));
    }
    return fmaxf(x, 0.0f) + log1pf(expf(-ax));
}
__device__ __forceinline__ float siluf(float x) { return x / (1.0f + __expf(-x)); }
__device__ __forceinline__ void split_fp16(float v, __half& h, __half& l) {
    h = __float2half(v);
    l = __float2half(v - __half2float(h));
}
__device__ __forceinline__ void load_h4(const __half* p, float* f) {
    uint2 v = *reinterpret_cast<const uint2*>(p);
    __half2 a = *reinterpret_cast<__half2*>(&v.x);
    __half2 b = *reinterpret_cast<__half2*>(&v.y);
    float2 fa = __half22float2(a), fb = __half22float2(b);
    f[0] = fa.x; f[1] = fa.y; f[2] = fb.x; f[3] = fb.y;
}

// ---------------- combined conversion kernel -------------------------------------
__global__ __launch_bounds__(256)
void cvt_all(const float* __restrict__ x, const float* __restrict__ inw,
             const float* __restrict__ outw, const float* __restrict__ dis,
             const float* __restrict__ xpw, const float* __restrict__ dtw)
{
    int b = blockIdx.x;
    if (b < 16384) {
        int i = b * 256 + threadIdx.x;
        float4 v = reinterpret_cast<const float4*>(x)[i];
        __half h[4] = { __float2half(v.x), __float2half(v.y),
                        __float2half(v.z), __float2half(v.w) };
        reinterpret_cast<uint2*>(g_xh)[i] = *reinterpret_cast<uint2*>(h);
    } else if (b < 16896) {
        int i = (b - 16384) * 256 + threadIdx.x;
        float4 v = reinterpret_cast<const float4*>(inw)[i];
        __half h[4], l[4];
        split_fp16(v.x, h[0], l[0]); split_fp16(v.y, h[1], l[1]);
        split_fp16(v.z, h[2], l[2]); split_fp16(v.w, h[3], l[3]);
        reinterpret_cast<uint2*>(g_wih)[i] = *reinterpret_cast<uint2*>(h);
        reinterpret_cast<uint2*>(g_wil)[i] = *reinterpret_cast<uint2*>(l);
    } else if (b < 17152) {
        int i = (b - 16896) * 256 + threadIdx.x;
        float4 v = reinterpret_cast<const float4*>(outw)[i];
        __half h[4], l[4];
        split_fp16(v.x, h[0], l[0]); split_fp16(v.y, h[1], l[1]);
        split_fp16(v.z, h[2], l[2]); split_fp16(v.w, h[3], l[3]);
        reinterpret_cast<uint2*>(g_woh)[i] = *reinterpret_cast<uint2*>(h);
        reinterpret_cast<uint2*>(g_wol)[i] = *reinterpret_cast<uint2*>(l);
    } else if (b < 18176) {
        int idx = (b - 17152) * 256 + threadIdx.x;
        int n = idx >> 9, k = idx & 511;
        g_dsh[idx] = __float2half(dis[k * 512 + n]);
    } else if (b < 18432) {
        int idx = (b - 18176) * 256 + threadIdx.x;
        int r = idx >> 9;
        __half h = __float2half(0.0f), l = h;
        if (r < 36) split_fp16(xpw[idx], h, l);
        g_xph[idx] = h; g_xpl[idx] = l;
    } else if (b < 18448) {
        int i = (b - 18432) * 256 + threadIdx.x;
        float4 v = reinterpret_cast<const float4*>(dtw)[i];
        __half h[4] = { __float2half(v.x), __float2half(v.y),
                        __float2half(v.z), __float2half(v.w) };
        reinterpret_cast<uint2*>(g_dtwh)[i] = *reinterpret_cast<uint2*>(h);
    } else {
        int n = (b - 18448) * 256 + threadIdx.x;
        float s = 0.0f;
        #pragma unroll 8
        for (int k = 0; k < 512; k++) s += dis[k * 512 + n];
        g_csum[n] = s * C_LN2;
    }
}

// ---------------- mma.sync fp16 GEMM ---------------------------------------------
// TERMS=2: C = A @ (Bh+Bl)^T.   TERMS=1: C = A @ Bh^T.
// EPI: 1 finite filter (fp32 out), 2 narrow (fp32 cols<ldc + fp16 cols<32 -> g_xbh),
//      4 in_proj split (cols<512 fp16 g_xsh; cols>=512 silu fp16 g_rsh),
//      5 fp16 store -> g_dph
#define PITCH   80
template <int EPI, int TERMS, int BN>
__global__ __launch_bounds__(256, 2)
void mma_gemm(const __half* __restrict__ A,
              const __half* __restrict__ Bh, const __half* __restrict__ Bl,
              float* __restrict__ C, int N, int K, int ldc)
{
    constexpr int WN = BN / 2;
    constexpr int TB = WN / 16;
    constexpr uint32_t BREG = BN * PITCH;
    constexpr uint32_t STAGE = 10240 + TERMS * BREG;

    extern __shared__ char dsm[];
    const uint32_t sb = smem_u32(dsm);
    const int tid = threadIdx.x;
    const int wid = tid >> 5, L = tid & 31;
    const int wm = wid >> 1, wn = wid & 1;
    const int m0 = blockIdx.y * 128, n0 = blockIdx.x * BN;

    const __half* srcA = A + (size_t)m0 * K;
    const __half* srcB[2] = { Bh + (size_t)n0 * K,
                              (TERMS == 2 ? Bl : Bh) + (size_t)n0 * K };

    const int lrow = L & 15;
    const int lcolB = (L >> 4) * 16;
    const uint32_t aBase = sb + (wm * 32 + lrow) * PITCH + lcolB;
    const uint32_t bBase = sb + 10240 + (wn * WN + lrow) * PITCH + lcolB;

    float acc[2][2 * TB][4];
    #pragma unroll
    for (int i = 0; i < 2; i++)
        #pragma unroll
        for (int j = 0; j < 2 * TB; j++)
            #pragma unroll
            for (int q = 0; q < 4; q++) acc[i][j][q] = 0.0f;

    const int nk = K / 32;

    auto load_stage = [&](int ks, int buf) {
        uint32_t dst0 = sb + buf * STAGE;
        int k0 = ks * 32;
        constexpr int ITERS = (512 + TERMS * BN * 4) / 256;
        #pragma unroll
        for (int it = 0; it < ITERS; it++) {
            int cid = it * 256 + tid;
            if (cid < 512) {
                int r = cid >> 2, c = cid & 3;
                CP_ASYNC16(dst0 + r * PITCH + c * 16, srcA + (size_t)r * K + k0 + c * 8);
            } else {
                int w2 = cid - 512;
                int matB = w2 / (BN * 4);
                int rw = w2 - matB * BN * 4;
                int r = rw >> 2, c = rw & 3;
                CP_ASYNC16(dst0 + 10240 + matB * BREG + r * PITCH + c * 16,
                           srcB[matB] + (size_t)r * K + k0 + c * 8);
            }
        }
    };

    load_stage(0, 0); CP_COMMIT();
    load_stage(1, 1); CP_COMMIT();

    for (int ks = 0; ks < nk; ks++) {
        CP_WAIT1();
        __syncthreads();
        uint32_t bo = (ks & 1) * STAGE;
        #pragma unroll
        for (int kk = 0; kk < 2; kk++) {
            uint32_t ko = kk * 32;
            uint32_t ah[2][4], b[TB][4];
            #pragma unroll
            for (int mi = 0; mi < 2; mi++)
                ldsm4(ah[mi], aBase + bo + mi * 1280 + ko);
            #pragma unroll
            for (int t = 0; t < TB; t++)
                ldsm4(b[t], bBase + bo + t * 1280 + ko);
            #pragma unroll
            for (int mi = 0; mi < 2; mi++)
                #pragma unroll
                for (int t = 0; t < TB; t++) {
                    mma16816(acc[mi][2*t+0], ah[mi], b[t][0], b[t][2]);
                    mma16816(acc[mi][2*t+1], ah[mi], b[t][1], b[t][3]);
                }
            if (TERMS == 2) {
                #pragma unroll
                for (int t = 0; t < TB; t++)
                    ldsm4(b[t], bBase + bo + BREG + t * 1280 + ko);
                #pragma unroll
                for (int mi = 0; mi < 2; mi++)
                    #pragma unroll
                    for (int t = 0; t < TB; t++) {
                        mma16816(acc[mi][2*t+0], ah[mi], b[t][0], b[t][2]);
                        mma16816(acc[mi][2*t+1], ah[mi], b[t][1], b[t][3]);
                    }
            }
        }
        __syncthreads();
        if (ks + 2 < nk) load_stage(ks + 2, ks & 1);
        CP_COMMIT();
    }

    // epilogue
    #pragma unroll
    for (int mi = 0; mi < 2; mi++) {
        #pragma unroll
        for (int j = 0; j < 2 * TB; j++) {
            int row = m0 + wm * 32 + mi * 16 + (L >> 2);
            int col = n0 + wn * WN + j * 8 + (L & 3) * 2;
            float v0 = acc[mi][j][0], v1 = acc[mi][j][1];
            float v2 = acc[mi][j][2], v3 = acc[mi][j][3];
            if (EPI == 1) {
                v0 = isfinite(v0) ? v0 : 0.0f; v1 = isfinite(v1) ? v1 : 0.0f;
                v2 = isfinite(v2) ? v2 : 0.0f; v3 = isfinite(v3) ? v3 : 0.0f;
                *reinterpret_cast<float2*>(C + (size_t)row * ldc + col)       = make_float2(v0, v1);
                *reinterpret_cast<float2*>(C + (size_t)(row + 8) * ldc + col) = make_float2(v2, v3);
            }
            if (EPI == 4) {
                __half p0[2], p1[2];
                if (col < 512) {
                    p0[0] = __float2half(v0); p0[1] = __float2half(v1);
                    p1[0] = __float2half(v2); p1[1] = __float2half(v3);
                    *reinterpret_cast<uint32_t*>(g_xsh + (size_t)row * 512 + col)       = *reinterpret_cast<uint32_t*>(p0);
                    *reinterpret_cast<uint32_t*>(g_xsh + (size_t)(row + 8) * 512 + col) = *reinterpret_cast<uint32_t*>(p1);
                } else {
                    int rc = col - 512;
                    p0[0] = __float2half(siluf(v0)); p0[1] = __float2half(siluf(v1));
                    p1[0] = __float2half(siluf(v2)); p1[1] = __float2half(siluf(v3));
                    *reinterpret_cast<uint32_t*>(g_rsh + (size_t)row * 512 + rc)       = *reinterpret_cast<uint32_t*>(p0);
                    *reinterpret_cast<uint32_t*>(g_rsh + (size_t)(row + 8) * 512 + rc) = *reinterpret_cast<uint32_t*>(p1);
                }
            }
            if (EPI == 5) {
                __half p0[2] = { __float2half(v0), __float2half(v1) };
                __half p1[2] = { __float2half(v2), __float2half(v3) };
                *reinterpret_cast<uint32_t*>(g_dph + (size_t)row * 512 + col)       = *reinterpret_cast<uint32_t*>(p0);
                *reinterpret_cast<uint32_t*>(g_dph + (size_t)(row + 8) * 512 + col) = *reinterpret_cast<uint32_t*>(p1);
            }
            if (EPI == 2) {
                if (col + 1 < ldc) {
                    *reinterpret_cast<float2*>(C + (size_t)row * ldc + col)       = make_float2(v0, v1);
                    *reinterpret_cast<float2*>(C + (size_t)(row + 8) * ldc + col) = make_float2(v2, v3);
                }
                if (col + 1 < 32) {
                    __half p0[2] = { __float2half(v0), __float2half(v1) };
                    __half p1[2] = { __float2half(v2), __float2half(v3) };
                    *reinterpret_cast<uint32_t*>(g_xbh + (size_t)row * 32 + col)       = *reinterpret_cast<uint32_t*>(p0);
                    *reinterpret_cast<uint32_t*>(g_xbh + (size_t)(row + 8) * 32 + col) = *reinterpret_cast<uint32_t*>(p1);
                }
            }
        }
    }
}

// ---------------- dtproj via tensor cores (K=32, single stage) -------------------
__global__ __launch_bounds__(256)
void dtproj_mma(const float* __restrict__ dtb)
{
    extern __shared__ char dsm[];
    const uint32_t sb = smem_u32(dsm);
    const int tid = threadIdx.x;
    const int wid = tid >> 5, L = tid & 31;
    const int wm = wid >> 1, wn = wid & 1;
    const int m0 = blockIdx.y * 128, n0 = blockIdx.x * 128;

    #pragma unroll
    for (int it = 0; it < 4; it++) {
        int cid = it * 256 + tid;
        int isB = cid >> 9, w = cid & 511;
        int r = w >> 2, c = w & 3;
        uint32_t dst = sb + isB * 10240 + r * PITCH + c * 16;
        const __half* src = isB ? (g_dtwh + (size_t)(n0 + r) * 32 + c * 8)
                                : (g_xbh + (size_t)(m0 + r) * 32 + c * 8);
        CP_ASYNC16(dst, src);
    }
    CP_COMMIT();
    CP_WAIT0();
    __syncthreads();

    const int lrow = L & 15;
    const int lcolB = (L >> 4) * 16;
    const uint32_t aBase = sb + (wm * 32 + lrow) * PITCH + lcolB;
    const uint32_t bBase = sb + 10240 + (wn * 64 + lrow) * PITCH + lcolB;

    float acc[2][8][4];
    #pragma unroll
    for (int i = 0; i < 2; i++)
        #pragma unroll
        for (int j = 0; j < 8; j++)
            #pragma unroll
            for (int q = 0; q < 4; q++) acc[i][j][q] = 0.0f;

    #pragma unroll
    for (int kk = 0; kk < 2; kk++) {
        uint32_t ko = kk * 32;
        uint32_t ah[2][4], b[4][4];
        #pragma unroll
        for (int mi = 0; mi < 2; mi++)
            ldsm4(ah[mi], aBase + mi * 1280 + ko);
        #pragma unroll
        for (int t = 0; t < 4; t++)
            ldsm4(b[t], bBase + t * 1280 + ko);
        #pragma unroll
        for (int mi = 0; mi < 2; mi++)
            #pragma unroll
            for (int t = 0; t < 4; t++) {
                mma16816(acc[mi][2*t+0], ah[mi], b[t][0], b[t][2]);
                mma16816(acc[mi][2*t+1], ah[mi], b[t][1], b[t][3]);
            }
    }

    #pragma unroll
    for (int mi = 0; mi < 2; mi++) {
        #pragma unroll
        for (int j = 0; j < 8; j++) {
            int row = m0 + wm * 32 + mi * 16 + (L >> 2);
            int col = n0 + wn * 64 + j * 8 + (L & 3) * 2;
            float b0 = dtb[col], b1 = dtb[col + 1];
            __half p0[2] = {
                __float2half(softplusf(acc[mi][j][0] + b0) - C_LN2),
                __float2half(softplusf(acc[mi][j][1] + b1) - C_LN2) };
            __half p1[2] = {
                __float2half(softplusf(acc[mi][j][2] + b0) - C_LN2),
                __float2half(softplusf(acc[mi][j][3] + b1) - C_LN2) };
            *reinterpret_cast<uint32_t*>(g_dh + (size_t)row * 512 + col)       = *reinterpret_cast<uint32_t*>(p0);
            *reinterpret_cast<uint32_t*>(g_dh + (size_t)(row + 8) * 512 + col) = *reinterpret_cast<uint32_t*>(p1);
        }
    }
}

// ---------------- depthwise conv + silu: fp16 in/out ------------------------------
__global__ __launch_bounds__(256)
void conv_silu_kernel(const float* __restrict__ cw, const float* __restrict__ cb)
{
    int g = blockIdx.x * 256 + threadIdx.x;
    int t0 = (g >> 7) * 4;
    int d4 = (g & 127) * 4;
    const __half* base = g_xsh + d4;

    float row[7][4];
    #pragma unroll
    for (int k = 0; k < 7; k++) {
        int t = t0 - 3 + k;
        if (t >= 0) load_h4(base + (size_t)t * 512, row[k]);
        else { row[k][0] = row[k][1] = row[k][2] = row[k][3] = 0.f; }
    }
    float4 bv = *reinterpret_cast<const float4*>(cb + d4);
    const float* bb = &bv.x;
    float4 w[4];
    #pragma unroll
    for (int j = 0; j < 4; j++) w[j] = reinterpret_cast<const float4*>(cw)[d4 + j];

    #pragma unroll
    for (int i = 0; i < 4; i++) {
        __half h[4];
        #pragma unroll
        for (int j = 0; j < 4; j++) {
            float a = bb[j];
            a = fmaf(w[j].x, row[i+0][j], a);
            a = fmaf(w[j].y, row[i+1][j], a);
            a = fmaf(w[j].z, row[i+2][j], a);
            a = fmaf(w[j].w, row[i+3][j], a);
            h[j] = __float2half(siluf(a));
        }
        *reinterpret_cast<uint2*>(g_uh + (size_t)(t0 + i) * 512 + d4) = *reinterpret_cast<uint2*>(h);
    }
}

// ---------------- scan passes (TCH=64, thread = 4 channels, fp16 inputs) ---------
__global__ __launch_bounds__(128)
void scanA_kernel(const float* __restrict__ Alog)
{
    int c  = blockIdx.x;
    int d4 = threadIdx.x * 4;
    float A0[4], A1[4], P0[4], P1[4], S0[4], S1[4];
    float4 cs4 = *reinterpret_cast<const float4*>(g_csum + d4);
    const float* cs = &cs4.x;
    #pragma unroll
    for (int j = 0; j < 4; j++) {
        A0[j] = -expf(Alog[(d4 + j) * 2 + 0]);
        A1[j] = -expf(Alog[(d4 + j) * 2 + 1]);
        P0[j] = 1.f; P1[j] = 1.f; S0[j] = 0.f; S1[j] = 0.f;
    }
    const __half* dp = g_dph + (size_t)c * TCH * DM + d4;
    const __half* uu = g_uh  + (size_t)c * TCH * DM + d4;
    const float*  xd = g_xdbl + (size_t)c * TCH * 36;
    #pragma unroll 4
    for (int i = 0; i < TCH; i++) {
        float rj[4], uj[4];
        load_h4(dp + (size_t)i * DM, rj);
        load_h4(uu + (size_t)i * DM, uj);
        float B0 = xd[i * 36 + 32], B1 = xd[i * 36 + 33];
        #pragma unroll
        for (int j = 0; j < 4; j++) {
            float dpv = cs[j] + rj[j];
            float x0 = dpv * A0[j], x1 = dpv * A1[j];
            float a0 = 0.f, a1 = 0.f;
            if (fmaxf(x0, x1) > -87.0f) { a0 = __expf(x0); a1 = __expf(x1); }
            float bu = dpv * uj[j];
            S0[j] = fmaf(a0, S0[j], bu * B0);
            S1[j] = fmaf(a1, S1[j], bu * B1);
            P0[j] *= a0; P1[j] *= a1;
        }
    }
    #pragma unroll
    for (int j = 0; j < 4; j++) {
        int dn = (d4 + j) * 2;
        g_P[c * 1024 + dn] = P0[j]; g_P[c * 1024 + dn + 1] = P1[j];
        g_S[c * 1024 + dn] = S0[j]; g_S[c * 1024 + dn + 1] = S1[j];
    }
}

__global__ __launch_bounds__(128)
void scanB_kernel()
{
    int dn = blockIdx.x * 128 + threadIdx.x;
    float h = 0.0f;
    for (int cb = 0; cb < NCH; cb += 16) {
        float p[16], s[16];
        #pragma unroll
        for (int i = 0; i < 16; i++) {
            p[i] = g_P[(cb + i) * 1024 + dn];
            s[i] = g_S[(cb + i) * 1024 + dn];
        }
        #pragma unroll
        for (int i = 0; i < 16; i++) {
            g_H[(cb + i) * 1024 + dn] = h;
            h = fmaf(p[i], h, s[i]);
        }
    }
}

__global__ __launch_bounds__(128)
void scanC_kernel(const float* __restrict__ Alog, const float* __restrict__ Dw)
{
    int c  = blockIdx.x;
    int d4 = threadIdx.x * 4;
    float A0[4], A1[4], h0[4], h1[4];
    float4 cs4 = *reinterpret_cast<const float4*>(g_csum + d4);
    const float* cs = &cs4.x;
    #pragma unroll
    for (int j = 0; j < 4; j++) {
        A0[j] = -expf(Alog[(d4 + j) * 2 + 0]);
        A1[j] = -expf(Alog[(d4 + j) * 2 + 1]);
        h0[j] = g_H[c * 1024 + (d4 + j) * 2];
        h1[j] = g_H[c * 1024 + (d4 + j) * 2 + 1];
    }
    float4 Dv4 = *reinterpret_cast<const float4*>(Dw + d4);
    const float* Dv = &Dv4.x;
    const __half* dp = g_dph + (size_t)c * TCH * DM + d4;
    const __half* uu = g_uh  + (size_t)c * TCH * DM + d4;
    const __half* rs = g_rsh + (size_t)c * TCH * DM + d4;
    const float*  xd = g_xdbl + (size_t)c * TCH * 36;
    __half* yh = g_yh + (size_t)c * TCH * DM + d4;
    #pragma unroll 4
    for (int i = 0; i < TCH; i++) {
        float pj[4], uj[4], rj[4];
        load_h4(dp + (size_t)i * DM, pj);
        load_h4(uu + (size_t)i * DM, uj);
        load_h4(rs + (size_t)i * DM, rj);
        float B0 = xd[i * 36 + 32], B1 = xd[i * 36 + 33];
        float C0 = xd[i * 36 + 34], C1 = xd[i * 36 + 35];
        __half oh[4];
        #pragma unroll
        for (int j = 0; j < 4; j++) {
            float dpv = cs[j] + pj[j];
            float x0 = dpv * A0[j], x1 = dpv * A1[j];
            float a0 = 0.f, a1 = 0.f;
            if (fmaxf(x0, x1) > -87.0f) { a0 = __expf(x0); a1 = __expf(x1); }
            float bu = dpv * uj[j];
            h0[j] = fmaf(a0, h0[j], bu * B0);
            h1[j] = fmaf(a1, h1[j], bu * B1);
            float y = fmaf(h0[j], C0, fmaf(h1[j], C1, uj[j] * Dv[j]));
            oh[j] = __float2half(y * rj[j]);
        }
        *reinterpret_cast<uint2*>(yh + (size_t)i * DM) = *reinterpret_cast<uint2*>(oh);
    }
}

// ---------------- launch --------------------------------------------------------
extern "C" void kernel_launch(void* const* d_in, const int* in_sizes, int n_in,
                              void* d_out, int out_size)
{
    const float* x     = (const float*)d_in[0];
    const float* dis   = (const float*)d_in[1];
    const float* inw   = (const float*)d_in[2];
    const float* convw = (const float*)d_in[3];
    const float* convb = (const float*)d_in[4];
    const float* xpw   = (const float*)d_in[5];
    const float* dtw   = (const float*)d_in[6];
    const float* dtb   = (const float*)d_in[7];
    const float* alog  = (const float*)d_in[8];
    const float* Dw    = (const float*)d_in[9];
    const float* outw  = (const float*)d_in[10];
    float* out = (float*)d_out;

    float *xdbl;
    __half *xh, *uh, *dh, *yh;
    __half *wih, *wil, *dsh, *woh, *wol, *xph, *xpl;
    cudaGetSymbolAddress((void**)&xdbl, g_xdbl);
    cudaGetSymbolAddress((void**)&xh,  g_xh);
    cudaGetSymbolAddress((void**)&uh,  g_uh);
    cudaGetSymbolAddress((void**)&dh,  g_dh);
    cudaGetSymbolAddress((void**)&yh,  g_yh);
    cudaGetSymbolAddress((void**)&wih, g_wih); cudaGetSymbolAddress((void**)&wil, g_wil);
    cudaGetSymbolAddress((void**)&dsh, g_dsh);
    cudaGetSymbolAddress((void**)&woh, g_woh); cudaGetSymbolAddress((void**)&wol, g_wol);
    cudaGetSymbolAddress((void**)&xph, g_xph); cudaGetSymbolAddress((void**)&xpl, g_xpl);

    const int SM2_128 = 2 * (10240 + 2 * 128 * PITCH);   // 61440
    const int SM2_64  = 2 * (10240 + 2 * 64  * PITCH);   // 40960
    const int SM1_128 = 2 * (10240 + 1 * 128 * PITCH);   // 40960
    cudaFuncSetAttribute((const void*)mma_gemm<4,2,128>, cudaFuncAttributeMaxDynamicSharedMemorySize, SM2_128);
    cudaFuncSetAttribute((const void*)mma_gemm<1,2,128>, cudaFuncAttributeMaxDynamicSharedMemorySize, SM2_128);
    cudaFuncSetAttribute((const void*)mma_gemm<2,2,64>,  cudaFuncAttributeMaxDynamicSharedMemorySize, SM2_64);
    cudaFuncSetAttribute((const void*)mma_gemm<5,1,128>, cudaFuncAttributeMaxDynamicSharedMemorySize, SM1_128);
    cudaFuncSetAttribute((const void*)dtproj_mma,        cudaFuncAttributeMaxDynamicSharedMemorySize, 20480);

    // 0) conversions + colsum
    cvt_all<<<18450, 256>>>(x, inw, outw, dis, xpw, dtw);

    // 1) in_proj: cols<512 -> fp16 g_xsh; cols>=512 -> silu fp16 g_rsh
    mma_gemm<4,2,128><<<dim3(8, SEQ / 128), 256, SM2_128>>>(xh, wih, wil, nullptr, 1024, 512, 1024);

    // 2) u = silu(conv(xs)) -> fp16
    conv_silu_kernel<<<(SEQ / 4 * 128) / 256, 256>>>(convw, convb);

    // 3) xdbl = u @ x_proj_w^T
    mma_gemm<2,2,64><<<dim3(1, SEQ / 128), 256, SM2_64>>>(uh, xph, xpl, xdbl, 64, 512, 36);

    // 4) delta residual via tensor cores
    dtproj_mma<<<dim3(DM / 128, SEQ / 128), 256, 20480>>>(dtb);

    // 5) delta_p residual -> fp16 g_dph (dp = csum + resid, reconstructed in scans)
    mma_gemm<5,1,128><<<dim3(DM / 128, SEQ / 128), 256, SM1_128>>>(dh, dsh, nullptr, nullptr, DM, 512, DM);

    // 6-8) chunked selective scan
    scanA_kernel<<<NCH, 128>>>(alog);
    scanB_kernel<<<8, 128>>>();
    scanC_kernel<<<NCH, 128>>>(alog, Dw);

    // 9) out = y @ out_proj_w^T, finite filter
    mma_gemm<1,2,128><<<dim3(DM / 128, SEQ / 128), 256, SM2_128>>>(yh, woh, wol, out, DM, 512, DM);
}